// round 2
// baseline (speedup 1.0000x reference)
#include <cuda_runtime.h>
#include <cuda_bf16.h>
#include <cstdint>
#include <cstddef>

// Problem constants
#define BB   8
#define CC   512
#define TT_  4096
#define HH   4
#define KK   16
#define VV   128
#define RR   15
#define NCH  208          // 64 q + 16 k + 128 v
#define NQ   64
#define NK   16
#define NV   128

// ---------------- scratch (__device__ globals; no allocation allowed) ----------------
__device__ float g_W[NCH * CC];                         // packed [208][512]
__device__ float g_proj[(size_t)BB * NCH * TT_];        // [8][208][4096]
__device__ float g_scale[192];                          // 0..63 q, 64..191 v
__device__ float g_shift[192];
__device__ float g_part[(size_t)BB * 32 * KK * VV];     // lambda_c partials
__device__ float g_lambda[(size_t)BB * KK * VV];        // [8][16][128]

// ---------------- pack W ----------------
__global__ void pack_w(const float* __restrict__ Wq, const float* __restrict__ Wk,
                       const float* __restrict__ Wv) {
    int i = blockIdx.x * 256 + threadIdx.x;
    if (i < NCH * CC) {
        int ch = i / CC, c = i % CC;
        float w;
        if (ch < 64)       w = Wq[ch * CC + c];
        else if (ch < 80)  w = Wk[(ch - 64) * CC + c];
        else               w = Wv[(ch - 80) * CC + c];
        g_W[i] = w;
    }
}

// ---------------- projection GEMM: proj[b][ch][t] = W[ch][:] . x[b][:][t] ----------------
// tile 64 ch x 128 t, k-chunk 16, double-buffered smem
#define G_TC 64
#define G_TT 128
#define G_KC 16

__global__ __launch_bounds__(256) void gemm_proj(const float* __restrict__ x) {
    __shared__ float sA[2][G_KC][G_TC];
    __shared__ float sB[2][G_KC][G_TT];
    const int tid = threadIdx.x;
    const int b = blockIdx.z, ctile = blockIdx.y, ttile = blockIdx.x;
    const int chBase = ctile * G_TC;
    const float* xb = x + (size_t)b * CC * TT_ + ttile * G_TT;
    float* ob = g_proj + ((size_t)b * NCH + chBase) * TT_ + ttile * G_TT;

    const int a_ch = tid >> 2, a_k = (tid & 3) * 4;
    const int b_k = tid >> 4, b_t = (tid & 15) * 8;

    float4 ra, rb0, rb1;
    const int my_ch = chBase + a_ch;

    // prologue loads
    if (my_ch < NCH) ra = *(const float4*)(g_W + (size_t)my_ch * CC + a_k);
    else             ra = make_float4(0.f, 0.f, 0.f, 0.f);
    {
        const float* p = xb + (size_t)b_k * TT_ + b_t;
        rb0 = *(const float4*)p; rb1 = *(const float4*)(p + 4);
    }
    sA[0][a_k + 0][a_ch] = ra.x; sA[0][a_k + 1][a_ch] = ra.y;
    sA[0][a_k + 2][a_ch] = ra.z; sA[0][a_k + 3][a_ch] = ra.w;
    *(float4*)&sB[0][b_k][b_t] = rb0;
    *(float4*)&sB[0][b_k][b_t + 4] = rb1;
    __syncthreads();

    float acc[8][4];
#pragma unroll
    for (int i = 0; i < 8; i++)
#pragma unroll
        for (int j = 0; j < 4; j++) acc[i][j] = 0.f;

    const int tr = (tid >> 5) << 3;
    const int tc = (tid & 31) << 2;
    const int NCHUNK = CC / G_KC; // 32

#pragma unroll 1
    for (int c = 0; c < NCHUNK; c++) {
        const int buf = c & 1;
        if (c + 1 < NCHUNK) {
            const int kc = (c + 1) * G_KC;
            if (my_ch < NCH) ra = *(const float4*)(g_W + (size_t)my_ch * CC + kc + a_k);
            else             ra = make_float4(0.f, 0.f, 0.f, 0.f);
            const float* p = xb + (size_t)(kc + b_k) * TT_ + b_t;
            rb0 = *(const float4*)p; rb1 = *(const float4*)(p + 4);
        }
#pragma unroll
        for (int k = 0; k < G_KC; k++) {
            const float4 a0 = *(const float4*)&sA[buf][k][tr];
            const float4 a1 = *(const float4*)&sA[buf][k][tr + 4];
            const float4 bv = *(const float4*)&sB[buf][k][tc];
            const float av[8] = {a0.x, a0.y, a0.z, a0.w, a1.x, a1.y, a1.z, a1.w};
            const float bw[4] = {bv.x, bv.y, bv.z, bv.w};
#pragma unroll
            for (int i = 0; i < 8; i++)
#pragma unroll
                for (int j = 0; j < 4; j++) acc[i][j] += av[i] * bw[j];
        }
        if (c + 1 < NCHUNK) {
            const int nb = buf ^ 1;
            sA[nb][a_k + 0][a_ch] = ra.x; sA[nb][a_k + 1][a_ch] = ra.y;
            sA[nb][a_k + 2][a_ch] = ra.z; sA[nb][a_k + 3][a_ch] = ra.w;
            *(float4*)&sB[nb][b_k][b_t] = rb0;
            *(float4*)&sB[nb][b_k][b_t + 4] = rb1;
        }
        __syncthreads();
    }

#pragma unroll
    for (int i = 0; i < 8; i++) {
        const int ch = chBase + tr + i;
        if (ch < NCH) {
            *(float4*)(ob + (size_t)(tr + i) * TT_ + tc) =
                make_float4(acc[i][0], acc[i][1], acc[i][2], acc[i][3]);
        }
    }
}

// ---------------- BN stats -> per-channel affine (scale, shift) ----------------
__global__ __launch_bounds__(256) void bn_stats(const float* __restrict__ gq, const float* __restrict__ bq,
                                                const float* __restrict__ gv, const float* __restrict__ bv) {
    const int ci = blockIdx.x;               // 0..191
    const int ch = ci < 64 ? ci : ci + 16;   // q rows 0..63, v rows 80..207
    const int tid = threadIdx.x;
    float s = 0.f, s2 = 0.f;
    for (int bb = 0; bb < BB; bb++) {
        const float* p = g_proj + ((size_t)bb * NCH + ch) * TT_;
        for (int i = tid * 4; i < TT_; i += 256 * 4) {
            float4 v = *(const float4*)(p + i);
            s += v.x + v.y + v.z + v.w;
            s2 += v.x * v.x + v.y * v.y + v.z * v.z + v.w * v.w;
        }
    }
    __shared__ float rs[256], rs2[256];
    rs[tid] = s; rs2[tid] = s2; __syncthreads();
    for (int o = 128; o > 0; o >>= 1) {
        if (tid < o) { rs[tid] += rs[tid + o]; rs2[tid] += rs2[tid + o]; }
        __syncthreads();
    }
    if (tid == 0) {
        const float N = (float)(BB * TT_);
        float mean = rs[0] / N;
        float var = rs2[0] / N - mean * mean;
        float g = ci < 64 ? gq[ci] : gv[ci - 64];
        float be = ci < 64 ? bq[ci] : bv[ci - 64];
        float sc = g * rsqrtf(var + 1e-5f);
        g_scale[ci] = sc;
        g_shift[ci] = be - mean * sc;
    }
}

// ---------------- softmax over t for k rows (in place) ----------------
__global__ __launch_bounds__(256) void softmax_k() {
    const int b = blockIdx.y, k = blockIdx.x;
    float* row = g_proj + ((size_t)b * NCH + 64 + k) * TT_;
    __shared__ float buf[TT_];
    __shared__ float red[256];
    const int tid = threadIdx.x;
    float m = -1e30f;
    for (int i = tid; i < TT_; i += 256) { float v = row[i]; buf[i] = v; m = fmaxf(m, v); }
    red[tid] = m; __syncthreads();
    for (int o = 128; o > 0; o >>= 1) { if (tid < o) red[tid] = fmaxf(red[tid], red[tid + o]); __syncthreads(); }
    m = red[0]; __syncthreads();
    float s = 0.f;
    for (int i = tid; i < TT_; i += 256) { float e = expf(buf[i] - m); buf[i] = e; s += e; }
    red[tid] = s; __syncthreads();
    for (int o = 128; o > 0; o >>= 1) { if (tid < o) red[tid] += red[tid + o]; __syncthreads(); }
    const float inv = 1.f / red[0];
    for (int i = tid; i < TT_; i += 256) row[i] = buf[i] * inv;
}

// ---------------- lambda_c partials: part[b][chunk][k][v] = sum_{t in chunk} ksm[k][t]*vraw[v][t] ----------------
__global__ __launch_bounds__(256) void lamc_part() {
    const int b = blockIdx.y, chunk = blockIdx.x;   // 32 chunks of 128 t
    const int t0 = chunk * 128;
    const float* pk = g_proj + ((size_t)b * NCH + 64) * TT_ + t0;
    const float* pv = g_proj + ((size_t)b * NCH + 80) * TT_ + t0;
    __shared__ float sk[KK][33];
    __shared__ float svt[32][132];
    const int tid = threadIdx.x;
    const int k = tid & 15, vg = tid >> 4;          // vg 0..15
    float acc[8];
#pragma unroll
    for (int j = 0; j < 8; j++) acc[j] = 0.f;

#pragma unroll 1
    for (int sub = 0; sub < 4; sub++) {
        for (int i = tid; i < KK * 32; i += 256) {
            int kk = i >> 5, tt = i & 31;
            sk[kk][tt] = pk[(size_t)kk * TT_ + sub * 32 + tt];
        }
        for (int i = tid; i < NV * 32; i += 256) {
            int v = i >> 5, tt = i & 31;
            svt[tt][v] = pv[(size_t)v * TT_ + sub * 32 + tt];
        }
        __syncthreads();
#pragma unroll
        for (int t = 0; t < 32; t++) {
            const float a = sk[k][t];
            const float4 v0 = *(const float4*)&svt[t][vg * 8];
            const float4 v1 = *(const float4*)&svt[t][vg * 8 + 4];
            acc[0] += a * v0.x; acc[1] += a * v0.y; acc[2] += a * v0.z; acc[3] += a * v0.w;
            acc[4] += a * v1.x; acc[5] += a * v1.y; acc[6] += a * v1.z; acc[7] += a * v1.w;
        }
        __syncthreads();
    }
    float* pp = g_part + (((size_t)b * 32 + chunk) * KK + k) * VV + vg * 8;
#pragma unroll
    for (int j = 0; j < 8; j++) pp[j] = acc[j];
}

// ---------------- reduce partials + fold v BN affine (sum_t ksm == 1) ----------------
__global__ void lamc_reduce() {
    const int i = blockIdx.x * 256 + threadIdx.x;   // < 8*16*128
    if (i >= BB * KK * VV) return;
    const int v = i & 127;
    const int b = i >> 11;
    const float* p = g_part + (size_t)b * 32 * KK * VV + (i & 2047);
    float s = 0.f;
#pragma unroll 1
    for (int c = 0; c < 32; c++) s += p[(size_t)c * KK * VV];
    g_lambda[i] = g_scale[64 + v] * s + g_shift[64 + v];
}

// ---------------- fused output: y = y_c + y_p ----------------
// y_c[h,v,t] = sum_k qhat[h,k,t] * lambda_c[k,v]
// y_p[h,v,t] = sum_r qw[h,r,t] * vhat[v,t-7+r] + qb[h,t],  qw = qhat . pos_w, qb = qhat . pos_b
#define M_TT 128
#define M_HW 144   // 128 + 14 halo, padded to 144

__global__ __launch_bounds__(256) void lambda_main(const float* __restrict__ pos_w,
                                                   const float* __restrict__ pos_b,
                                                   float* __restrict__ out) {
    extern __shared__ float sm[];
    float* sq  = sm;                 // [64][128]
    float* sv  = sm + NQ * M_TT;     // [128][144]
    float* slc = sv + NV * M_HW;     // [16][128]
    float* spw = slc + KK * VV;      // [16*15]
    float* spb = spw + KK * RR;      // [16]

    const int b = blockIdx.y;
    const int t0 = blockIdx.x * M_TT;
    const int tid = threadIdx.x;
    const float* pq = g_proj + (size_t)b * NCH * TT_;
    const float* pv = pq + (size_t)80 * TT_;

    for (int i = tid; i < NQ * M_TT; i += 256) {
        int ch = i >> 7, t = i & 127;
        sq[i] = pq[(size_t)ch * TT_ + t0 + t] * g_scale[ch] + g_shift[ch];
    }
    for (int i = tid; i < NV * M_HW; i += 256) {
        int v = i / M_HW, tr = i % M_HW;
        float val = 0.f;
        if (tr < M_TT + RR - 1) {
            int tg = t0 - (RR / 2) + tr;
            if (tg >= 0 && tg < TT_)
                val = pv[(size_t)v * TT_ + tg] * g_scale[64 + v] + g_shift[64 + v];
        }
        sv[i] = val;
    }
    for (int i = tid; i < KK * VV; i += 256) slc[i] = g_lambda[(size_t)b * KK * VV + i];
    if (tid < KK * RR) spw[tid] = pos_w[tid];
    if (tid < KK) spb[tid] = pos_b[tid];
    __syncthreads();

    const int t = tid & 127;
    const int vh = tid >> 7;

    float q[NQ];
#pragma unroll
    for (int ch = 0; ch < NQ; ch++) q[ch] = sq[ch * M_TT + t];

    float qw[HH][RR];
    float qb[HH] = {0.f, 0.f, 0.f, 0.f};
#pragma unroll
    for (int h = 0; h < HH; h++)
#pragma unroll
        for (int r = 0; r < RR; r++) qw[h][r] = 0.f;

#pragma unroll
    for (int k = 0; k < KK; k++) {
        const float pb = spb[k];
#pragma unroll
        for (int h = 0; h < HH; h++) qb[h] += q[h * KK + k] * pb;
#pragma unroll
        for (int r = 0; r < RR; r++) {
            const float w = spw[k * RR + r];
#pragma unroll
            for (int h = 0; h < HH; h++) qw[h][r] += q[h * KK + k] * w;
        }
    }

    float* ob = out + (size_t)b * 512 * TT_ + t0 + t;
#pragma unroll 2
    for (int v = 0; v < 64; v++) {
        const int vv = vh * 64 + v;
        float a0 = qb[0], a1 = qb[1], a2 = qb[2], a3 = qb[3];
#pragma unroll
        for (int k = 0; k < KK; k++) {
            const float l = slc[k * VV + vv];
            a0 += q[k] * l;
            a1 += q[KK + k] * l;
            a2 += q[2 * KK + k] * l;
            a3 += q[3 * KK + k] * l;
        }
        const float* vp = sv + vv * M_HW + t;
#pragma unroll
        for (int r = 0; r < RR; r++) {
            const float x = vp[r];
            a0 += qw[0][r] * x;
            a1 += qw[1][r] * x;
            a2 += qw[2][r] * x;
            a3 += qw[3][r] * x;
        }
        ob[(size_t)(0 * VV + vv) * TT_] = a0;
        ob[(size_t)(1 * VV + vv) * TT_] = a1;
        ob[(size_t)(2 * VV + vv) * TT_] = a2;
        ob[(size_t)(3 * VV + vv) * TT_] = a3;
    }
}

// ---------------- launch ----------------
extern "C" void kernel_launch(void* const* d_in, const int* in_sizes, int n_in,
                              void* d_out, int out_size) {
    const float* x  = (const float*)d_in[0];
    const float* Wq = (const float*)d_in[1];
    const float* Wk = (const float*)d_in[2];
    const float* Wv = (const float*)d_in[3];
    const float* gq = (const float*)d_in[4];
    const float* bq = (const float*)d_in[5];
    const float* gv = (const float*)d_in[6];
    const float* bv = (const float*)d_in[7];
    const float* pw = (const float*)d_in[8];
    const float* pb = (const float*)d_in[9];
    float* out = (float*)d_out;

    const size_t main_smem = (size_t)(NQ * M_TT + NV * M_HW + KK * VV + KK * RR + KK) * sizeof(float);
    cudaFuncSetAttribute(lambda_main, cudaFuncAttributeMaxDynamicSharedMemorySize, (int)main_smem);

    pack_w<<<(NCH * CC + 255) / 256, 256>>>(Wq, Wk, Wv);
    gemm_proj<<<dim3(TT_ / G_TT, 4, BB), 256>>>(x);
    bn_stats<<<192, 256>>>(gq, bq, gv, bv);
    softmax_k<<<dim3(KK, BB), 256>>>();
    lamc_part<<<dim3(32, BB), 256>>>();
    lamc_reduce<<<(BB * KK * VV + 255) / 256, 256>>>();
    lambda_main<<<dim3(TT_ / M_TT, BB), 256, main_smem>>>(pw, pb, out);
}

// round 9
// speedup vs baseline: 1.4445x; 1.4445x over previous
#include <cuda_runtime.h>
#include <cuda_bf16.h>
#include <cstdint>
#include <cstddef>

// Problem constants
#define BB   8
#define CC   512
#define TT_  4096
#define HH   4
#define KK   16
#define VV   128
#define RR   15
#define NCH  208          // 64 q + 16 k + 128 v
#define NQ   64
#define NV   128
#define MPAD 256
#define NT   32768        // BB*TT_
#define NCHUNKS 24        // K-concat 1536 / 64

// ---------------- scratch ----------------
__device__ float g_proj[(size_t)BB * NCH * TT_];        // [8][208][4096]
__device__ float g_scale[192];
__device__ float g_shift[192];
__device__ float g_part[(size_t)BB * 32 * KK * VV];
__device__ float g_lambda[(size_t)BB * KK * VV];
__device__ __nv_bfloat16 g_Wh[MPAD * CC];
__device__ __nv_bfloat16 g_Wl[MPAD * CC];
__device__ __nv_bfloat16 g_xh[(size_t)NT * CC];         // [b*t][c]
__device__ __nv_bfloat16 g_xl[(size_t)NT * CC];

// ---------------- helpers ----------------
__device__ __forceinline__ uint32_t smem_u32(const void* p) {
    uint32_t a;
    asm("{ .reg .u64 t; cvta.to.shared.u64 t, %1; cvt.u32.u64 %0, t; }" : "=r"(a) : "l"(p));
    return a;
}
#define SWZ128(off) ((off) ^ (((off) >> 3) & 0x70))
#define CP_ASYNC16(dst, src) \
    asm volatile("cp.async.cg.shared.global [%0], [%1], 16;" :: "r"(dst), "l"(src))

__device__ __forceinline__ void ldsm_x4(uint32_t& r0, uint32_t& r1, uint32_t& r2, uint32_t& r3,
                                        uint32_t addr) {
    asm volatile("ldmatrix.sync.aligned.m8n8.x4.shared.b16 {%0,%1,%2,%3}, [%4];"
        : "=r"(r0), "=r"(r1), "=r"(r2), "=r"(r3) : "r"(addr));
}
#define MMA16816(c, a, b0, b1) \
    asm volatile("mma.sync.aligned.m16n8k16.row.col.f32.bf16.bf16.f32 " \
        "{%0,%1,%2,%3}, {%4,%5,%6,%7}, {%8,%9}, {%0,%1,%2,%3};" \
        : "+f"((c)[0]), "+f"((c)[1]), "+f"((c)[2]), "+f"((c)[3]) \
        : "r"((a)[0]), "r"((a)[1]), "r"((a)[2]), "r"((a)[3]), "r"(b0), "r"(b1))

// ---------------- pack W, split into bf16 hi/lo (padded to 256 rows) ----------------
__global__ void pack_w_split(const float* __restrict__ Wq, const float* __restrict__ Wk,
                             const float* __restrict__ Wv) {
    int i = blockIdx.x * 256 + threadIdx.x;
    if (i >= MPAD * CC) return;
    int ch = i / CC, c = i % CC;
    float w = 0.f;
    if (ch < 64)       w = Wq[ch * CC + c];
    else if (ch < 80)  w = Wk[(ch - 64) * CC + c];
    else if (ch < NCH) w = Wv[(ch - 80) * CC + c];
    __nv_bfloat16 h = __float2bfloat16(w);
    g_Wh[i] = h;
    g_Wl[i] = __float2bfloat16(w - __bfloat162float(h));
}

// ---------------- transpose + split x: [b][c][t] f32 -> [b*t][c] bf16 hi/lo ----------------
__global__ __launch_bounds__(256) void xsplit(const float* __restrict__ x) {
    __shared__ float s[32][33];
    const int b = blockIdx.z, c0 = blockIdx.y * 32, t0 = blockIdx.x * 32;
    const int tx = threadIdx.x & 31, ty = threadIdx.x >> 5;   // ty 0..7
    const float* xp = x + ((size_t)b * CC + c0) * TT_ + t0;
#pragma unroll
    for (int j = 0; j < 4; j++)
        s[tx][ty + j * 8] = xp[(size_t)(ty + j * 8) * TT_ + tx];
    __syncthreads();
    const size_t row0 = (size_t)b * TT_ + t0;
#pragma unroll
    for (int j = 0; j < 4; j++) {
        int tr = ty + j * 8;
        float v = s[tr][tx];
        __nv_bfloat16 h = __float2bfloat16(v);
        g_xh[(row0 + tr) * CC + c0 + tx] = h;
        g_xl[(row0 + tr) * CC + c0 + tx] = __float2bfloat16(v - __bfloat162float(h));
    }
}

// ---------------- mma.sync bf16 projection GEMM ----------------
// D[ch][gt] = sum over K-concat 1536: [Wh|Wh|Wl][ch][k] * [xh|xl|xh][gt][k]
// CTA 128x128, 8 warps (2M x 4N), warp 64x32, K-stage 64, double-buffered.
#define GM_SMEM 65536

__global__ __launch_bounds__(256) void gemm_mma() {
    extern __shared__ __align__(128) char smem[];
    const uint32_t sb = smem_u32(smem);
    const int tid = threadIdx.x;
    const int wid = tid >> 5, lane = tid & 31;
    const int n0 = blockIdx.x * 128;       // flattened b*t column base
    const int m0 = blockIdx.y * 128;       // channel base
    const int wm = wid & 1, wn = wid >> 1; // warp tile origin

    auto issue = [&](int c) {
        const __nv_bfloat16 *aseg, *bseg;
        int koff;
        if (c < 8)       { aseg = g_Wh; bseg = g_xh; koff = c * 64; }
        else if (c < 16) { aseg = g_Wh; bseg = g_xl; koff = (c - 8) * 64; }
        else             { aseg = g_Wl; bseg = g_xh; koff = (c - 16) * 64; }
        const uint32_t st = sb + (c & 1) * 32768;
#pragma unroll
        for (int j = 0; j < 4; j++) {
            int idx = tid + j * 256;
            int r = idx >> 3, cc = idx & 7;
            CP_ASYNC16(st + SWZ128((uint32_t)(r * 128 + cc * 16)),
                       aseg + (size_t)(m0 + r) * CC + koff + cc * 8);
        }
#pragma unroll
        for (int j = 0; j < 4; j++) {
            int idx = tid + j * 256;
            int r = idx >> 3, cc = idx & 7;
            CP_ASYNC16(st + 16384 + SWZ128((uint32_t)(r * 128 + cc * 16)),
                       bseg + (size_t)(n0 + r) * CC + koff + cc * 8);
        }
        asm volatile("cp.async.commit_group;");
    };

    float acc[4][4][4];
#pragma unroll
    for (int i = 0; i < 4; i++)
#pragma unroll
        for (int j = 0; j < 4; j++)
#pragma unroll
            for (int k = 0; k < 4; k++) acc[i][j][k] = 0.f;

    const int ml = lane >> 3, rin = lane & 7;

    issue(0);
#pragma unroll 1
    for (int i = 0; i < NCHUNKS; i++) {
        if (i + 1 < NCHUNKS) {
            issue(i + 1);
            asm volatile("cp.async.wait_group 1;");
        } else {
            asm volatile("cp.async.wait_group 0;");
        }
        __syncthreads();
        const uint32_t stA = sb + (i & 1) * 32768;
        const uint32_t stB = stA + 16384;
#pragma unroll
        for (int ks = 0; ks < 4; ks++) {
            uint32_t a[4][4];
#pragma unroll
            for (int mi = 0; mi < 4; mi++) {
                const int row = wm * 64 + mi * 16 + (ml & 1) * 8 + rin;
                const int kc = 2 * ks + (ml >> 1);
                ldsm_x4(a[mi][0], a[mi][1], a[mi][2], a[mi][3],
                        stA + row * 128 + ((kc ^ (row & 7)) << 4));
            }
            uint32_t bfr[2][4];
#pragma unroll
            for (int bi = 0; bi < 2; bi++) {
                const int n = wn * 32 + bi * 16 + (ml >> 1) * 8 + rin;
                const int kc = 2 * ks + (ml & 1);
                ldsm_x4(bfr[bi][0], bfr[bi][1], bfr[bi][2], bfr[bi][3],
                        stB + n * 128 + ((kc ^ (n & 7)) << 4));
            }
#pragma unroll
            for (int mi = 0; mi < 4; mi++)
#pragma unroll
                for (int ni = 0; ni < 4; ni++)
                    MMA16816(acc[mi][ni], a[mi],
                             bfr[ni >> 1][(ni & 1) * 2], bfr[ni >> 1][(ni & 1) * 2 + 1]);
        }
        __syncthreads();
    }

    // epilogue: c0,c1 at (row, col..col+1); c2,c3 at (row+8, col..col+1)
    const int b = n0 >> 12;
    const int t0 = n0 & (TT_ - 1);
#pragma unroll
    for (int mi = 0; mi < 4; mi++) {
#pragma unroll
        for (int h = 0; h < 2; h++) {
            const int ch = m0 + wm * 64 + mi * 16 + (lane >> 2) + h * 8;
            if (ch < NCH) {
                float* p = g_proj + ((size_t)b * NCH + ch) * TT_ + t0 + wn * 32 + (lane & 3) * 2;
#pragma unroll
                for (int ni = 0; ni < 4; ni++) {
                    float2 v = make_float2(acc[mi][ni][h * 2], acc[mi][ni][h * 2 + 1]);
                    *(float2*)(p + ni * 8) = v;
                }
            }
        }
    }
}

// ---------------- BN stats -> per-channel affine ----------------
__global__ __launch_bounds__(256) void bn_stats(const float* __restrict__ gq, const float* __restrict__ bq,
                                                const float* __restrict__ gv, const float* __restrict__ bv) {
    const int ci = blockIdx.x;
    const int ch = ci < 64 ? ci : ci + 16;
    const int tid = threadIdx.x;
    float s = 0.f, s2 = 0.f;
    for (int bb = 0; bb < BB; bb++) {
        const float* p = g_proj + ((size_t)bb * NCH + ch) * TT_;
        for (int i = tid * 4; i < TT_; i += 256 * 4) {
            float4 v = *(const float4*)(p + i);
            s += v.x + v.y + v.z + v.w;
            s2 += v.x * v.x + v.y * v.y + v.z * v.z + v.w * v.w;
        }
    }
    __shared__ float rs[256], rs2[256];
    rs[tid] = s; rs2[tid] = s2; __syncthreads();
    for (int o = 128; o > 0; o >>= 1) {
        if (tid < o) { rs[tid] += rs[tid + o]; rs2[tid] += rs2[tid + o]; }
        __syncthreads();
    }
    if (tid == 0) {
        const float N = (float)(BB * TT_);
        float mean = rs[0] / N;
        float var = rs2[0] / N - mean * mean;
        float g = ci < 64 ? gq[ci] : gv[ci - 64];
        float be = ci < 64 ? bq[ci] : bv[ci - 64];
        float sc = g * rsqrtf(var + 1e-5f);
        g_scale[ci] = sc;
        g_shift[ci] = be - mean * sc;
    }
}

// ---------------- softmax over t for k rows (in place) ----------------
__global__ __launch_bounds__(256) void softmax_k() {
    const int b = blockIdx.y, k = blockIdx.x;
    float* row = g_proj + ((size_t)b * NCH + 64 + k) * TT_;
    __shared__ float buf[TT_];
    __shared__ float red[256];
    const int tid = threadIdx.x;
    float m = -1e30f;
    for (int i = tid; i < TT_; i += 256) { float v = row[i]; buf[i] = v; m = fmaxf(m, v); }
    red[tid] = m; __syncthreads();
    for (int o = 128; o > 0; o >>= 1) { if (tid < o) red[tid] = fmaxf(red[tid], red[tid + o]); __syncthreads(); }
    m = red[0]; __syncthreads();
    float s = 0.f;
    for (int i = tid; i < TT_; i += 256) { float e = expf(buf[i] - m); buf[i] = e; s += e; }
    red[tid] = s; __syncthreads();
    for (int o = 128; o > 0; o >>= 1) { if (tid < o) red[tid] += red[tid + o]; __syncthreads(); }
    const float inv = 1.f / red[0];
    for (int i = tid; i < TT_; i += 256) row[i] = buf[i] * inv;
}

// ---------------- lambda_c partials ----------------
__global__ __launch_bounds__(256) void lamc_part() {
    const int b = blockIdx.y, chunk = blockIdx.x;
    const int t0 = chunk * 128;
    const float* pk = g_proj + ((size_t)b * NCH + 64) * TT_ + t0;
    const float* pv = g_proj + ((size_t)b * NCH + 80) * TT_ + t0;
    __shared__ float sk[KK][33];
    __shared__ float svt[32][132];
    const int tid = threadIdx.x;
    const int k = tid & 15, vg = tid >> 4;
    float acc[8];
#pragma unroll
    for (int j = 0; j < 8; j++) acc[j] = 0.f;

#pragma unroll 1
    for (int sub = 0; sub < 4; sub++) {
        for (int i = tid; i < KK * 32; i += 256) {
            int kk = i >> 5, tt = i & 31;
            sk[kk][tt] = pk[(size_t)kk * TT_ + sub * 32 + tt];
        }
        for (int i = tid; i < NV * 32; i += 256) {
            int v = i >> 5, tt = i & 31;
            svt[tt][v] = pv[(size_t)v * TT_ + sub * 32 + tt];
        }
        __syncthreads();
#pragma unroll
        for (int t = 0; t < 32; t++) {
            const float a = sk[k][t];
            const float4 v0 = *(const float4*)&svt[t][vg * 8];
            const float4 v1 = *(const float4*)&svt[t][vg * 8 + 4];
            acc[0] += a * v0.x; acc[1] += a * v0.y; acc[2] += a * v0.z; acc[3] += a * v0.w;
            acc[4] += a * v1.x; acc[5] += a * v1.y; acc[6] += a * v1.z; acc[7] += a * v1.w;
        }
        __syncthreads();
    }
    float* pp = g_part + (((size_t)b * 32 + chunk) * KK + k) * VV + vg * 8;
#pragma unroll
    for (int j = 0; j < 8; j++) pp[j] = acc[j];
}

// ---------------- reduce partials + fold v BN affine ----------------
__global__ void lamc_reduce() {
    const int i = blockIdx.x * 256 + threadIdx.x;
    if (i >= BB * KK * VV) return;
    const int v = i & 127;
    const int b = i >> 11;
    const float* p = g_part + (size_t)b * 32 * KK * VV + (i & 2047);
    float s = 0.f;
#pragma unroll 1
    for (int c = 0; c < 32; c++) s += p[(size_t)c * KK * VV];
    g_lambda[i] = g_scale[64 + v] * s + g_shift[64 + v];
}

// ---------------- fused output ----------------
#define M_TT 128
#define M_HW 144

__global__ __launch_bounds__(256) void lambda_main(const float* __restrict__ pos_w,
                                                   const float* __restrict__ pos_b,
                                                   float* __restrict__ out) {
    extern __shared__ float sm[];
    float* sq  = sm;
    float* sv  = sm + NQ * M_TT;
    float* slc = sv + NV * M_HW;
    float* spw = slc + KK * VV;
    float* spb = spw + KK * RR;

    const int b = blockIdx.y;
    const int t0 = blockIdx.x * M_TT;
    const int tid = threadIdx.x;
    const float* pq = g_proj + (size_t)b * NCH * TT_;
    const float* pv = pq + (size_t)80 * TT_;

    for (int i = tid; i < NQ * M_TT; i += 256) {
        int ch = i >> 7, t = i & 127;
        sq[i] = pq[(size_t)ch * TT_ + t0 + t] * g_scale[ch] + g_shift[ch];
    }
    for (int i = tid; i < NV * M_HW; i += 256) {
        int v = i / M_HW, tr = i % M_HW;
        float val = 0.f;
        if (tr < M_TT + RR - 1) {
            int tg = t0 - (RR / 2) + tr;
            if (tg >= 0 && tg < TT_)
                val = pv[(size_t)v * TT_ + tg] * g_scale[64 + v] + g_shift[64 + v];
        }
        sv[i] = val;
    }
    for (int i = tid; i < KK * VV; i += 256) slc[i] = g_lambda[(size_t)b * KK * VV + i];
    if (tid < KK * RR) spw[tid] = pos_w[tid];
    if (tid < KK) spb[tid] = pos_b[tid];
    __syncthreads();

    const int t = tid & 127;
    const int vh = tid >> 7;

    float q[NQ];
#pragma unroll
    for (int ch = 0; ch < NQ; ch++) q[ch] = sq[ch * M_TT + t];

    float qw[HH][RR];
    float qb[HH] = {0.f, 0.f, 0.f, 0.f};
#pragma unroll
    for (int h = 0; h < HH; h++)
#pragma unroll
        for (int r = 0; r < RR; r++) qw[h][r] = 0.f;

#pragma unroll
    for (int k = 0; k < KK; k++) {
        const float pb = spb[k];
#pragma unroll
        for (int h = 0; h < HH; h++) qb[h] += q[h * KK + k] * pb;
#pragma unroll
        for (int r = 0; r < RR; r++) {
            const float w = spw[k * RR + r];
#pragma unroll
            for (int h = 0; h < HH; h++) qw[h][r] += q[h * KK + k] * w;
        }
    }

    float* ob = out + (size_t)b * 512 * TT_ + t0 + t;
#pragma unroll 2
    for (int v = 0; v < 64; v++) {
        const int vv = vh * 64 + v;
        float a0 = qb[0], a1 = qb[1], a2 = qb[2], a3 = qb[3];
#pragma unroll
        for (int k = 0; k < KK; k++) {
            const float l = slc[k * VV + vv];
            a0 += q[k] * l;
            a1 += q[KK + k] * l;
            a2 += q[2 * KK + k] * l;
            a3 += q[3 * KK + k] * l;
        }
        const float* vp = sv + vv * M_HW + t;
#pragma unroll
        for (int r = 0; r < RR; r++) {
            const float x = vp[r];
            a0 += qw[0][r] * x;
            a1 += qw[1][r] * x;
            a2 += qw[2][r] * x;
            a3 += qw[3][r] * x;
        }
        ob[(size_t)(0 * VV + vv) * TT_] = a0;
        ob[(size_t)(1 * VV + vv) * TT_] = a1;
        ob[(size_t)(2 * VV + vv) * TT_] = a2;
        ob[(size_t)(3 * VV + vv) * TT_] = a3;
    }
}

// ---------------- launch ----------------
extern "C" void kernel_launch(void* const* d_in, const int* in_sizes, int n_in,
                              void* d_out, int out_size) {
    const float* x  = (const float*)d_in[0];
    const float* Wq = (const float*)d_in[1];
    const float* Wk = (const float*)d_in[2];
    const float* Wv = (const float*)d_in[3];
    const float* gq = (const float*)d_in[4];
    const float* bq = (const float*)d_in[5];
    const float* gv = (const float*)d_in[6];
    const float* bv = (const float*)d_in[7];
    const float* pw = (const float*)d_in[8];
    const float* pb = (const float*)d_in[9];
    float* out = (float*)d_out;

    const size_t main_smem = (size_t)(NQ * M_TT + NV * M_HW + KK * VV + KK * RR + KK) * sizeof(float);
    cudaFuncSetAttribute(lambda_main, cudaFuncAttributeMaxDynamicSharedMemorySize, (int)main_smem);
    cudaFuncSetAttribute(gemm_mma, cudaFuncAttributeMaxDynamicSharedMemorySize, GM_SMEM);

    pack_w_split<<<(MPAD * CC + 255) / 256, 256>>>(Wq, Wk, Wv);
    xsplit<<<dim3(TT_ / 32, CC / 32, BB), 256>>>(x);
    gemm_mma<<<dim3(NT / 128, 2), 256, GM_SMEM>>>();
    bn_stats<<<192, 256>>>(gq, bq, gv, bv);
    softmax_k<<<dim3(KK, BB), 256>>>();
    lamc_part<<<dim3(32, BB), 256>>>();
    lamc_reduce<<<(BB * KK * VV + 255) / 256, 256>>>();
    lambda_main<<<dim3(TT_ / M_TT, BB), 256, main_smem>>>(pw, pb, out);
}

// round 10
// speedup vs baseline: 1.4901x; 1.0315x over previous
#include <cuda_runtime.h>
#include <cuda_bf16.h>
#include <cstdint>
#include <cstddef>

// Problem constants
#define BB   8
#define CC   512
#define TT_  4096
#define HH   4
#define KK   16
#define VV   128
#define RR   15
#define NCH  208          // 64 q + 16 k + 128 v
#define NQ   64
#define NV   128
#define MPAD 256
#define NT   32768        // BB*TT_
#define PSTG 16           // paired stages: 8x (xh: Wh+Wl) + 8x (xl: Wh)

// ---------------- scratch ----------------
__device__ float g_proj[(size_t)BB * NCH * TT_];        // [8][208][4096]
__device__ float g_scale[192];
__device__ float g_shift[192];
__device__ float g_part[(size_t)BB * 32 * KK * VV];
__device__ float g_lambda[(size_t)BB * KK * VV];
__device__ float g_bnp[192 * 8 * 2];
__device__ __nv_bfloat16 g_Wh[MPAD * CC];
__device__ __nv_bfloat16 g_Wl[MPAD * CC];
__device__ __nv_bfloat16 g_xh[(size_t)NT * CC];         // [b*t][c]
__device__ __nv_bfloat16 g_xl[(size_t)NT * CC];

// ---------------- helpers ----------------
__device__ __forceinline__ uint32_t smem_u32(const void* p) {
    uint32_t a;
    asm("{ .reg .u64 t; cvta.to.shared.u64 t, %1; cvt.u32.u64 %0, t; }" : "=r"(a) : "l"(p));
    return a;
}
#define SWZ128(off) ((off) ^ (((off) >> 3) & 0x70))
#define CP_ASYNC16(dst, src) \
    asm volatile("cp.async.cg.shared.global [%0], [%1], 16;" :: "r"(dst), "l"(src))

__device__ __forceinline__ void ldsm_x4(uint32_t& r0, uint32_t& r1, uint32_t& r2, uint32_t& r3,
                                        uint32_t addr) {
    asm volatile("ldmatrix.sync.aligned.m8n8.x4.shared.b16 {%0,%1,%2,%3}, [%4];"
        : "=r"(r0), "=r"(r1), "=r"(r2), "=r"(r3) : "r"(addr));
}
#define MMA16816(c, a, b0, b1) \
    asm volatile("mma.sync.aligned.m16n8k16.row.col.f32.bf16.bf16.f32 " \
        "{%0,%1,%2,%3}, {%4,%5,%6,%7}, {%8,%9}, {%0,%1,%2,%3};" \
        : "+f"((c)[0]), "+f"((c)[1]), "+f"((c)[2]), "+f"((c)[3]) \
        : "r"((a)[0]), "r"((a)[1]), "r"((a)[2]), "r"((a)[3]), "r"(b0), "r"(b1))

// ---------------- pack W, split into bf16 hi/lo (padded to 256 rows) ----------------
__global__ void pack_w_split(const float* __restrict__ Wq, const float* __restrict__ Wk,
                             const float* __restrict__ Wv) {
    int i = blockIdx.x * 256 + threadIdx.x;
    if (i >= MPAD * CC) return;
    int ch = i / CC, c = i % CC;
    float w = 0.f;
    if (ch < 64)       w = Wq[ch * CC + c];
    else if (ch < 80)  w = Wk[(ch - 64) * CC + c];
    else if (ch < NCH) w = Wv[(ch - 80) * CC + c];
    __nv_bfloat16 h = __float2bfloat16(w);
    g_Wh[i] = h;
    g_Wl[i] = __float2bfloat16(w - __bfloat162float(h));
}

// ---------------- transpose + split x: [b][c][t] f32 -> [b*t][c] bf16 hi/lo ----------------
__global__ __launch_bounds__(256) void xsplit(const float* __restrict__ x, int b0) {
    __shared__ float s[32][33];
    const int b = blockIdx.z + b0, c0 = blockIdx.y * 32, t0 = blockIdx.x * 32;
    const int tx = threadIdx.x & 31, ty = threadIdx.x >> 5;   // ty 0..7
    const float* xp = x + ((size_t)b * CC + c0) * TT_ + t0;
#pragma unroll
    for (int j = 0; j < 4; j++)
        s[tx][ty + j * 8] = xp[(size_t)(ty + j * 8) * TT_ + tx];
    __syncthreads();
    const size_t row0 = (size_t)b * TT_ + t0;
#pragma unroll
    for (int j = 0; j < 4; j++) {
        int tr = ty + j * 8;
        float v = s[tr][tx];
        __nv_bfloat16 h = __float2bfloat16(v);
        g_xh[(row0 + tr) * CC + c0 + tx] = h;
        g_xl[(row0 + tr) * CC + c0 + tx] = __float2bfloat16(v - __bfloat162float(h));
    }
}

// ---------------- mma.sync bf16 projection GEMM (paired stages) ----------------
// D[ch][gt] = Wh.xh + Wl.xh + Wh.xl  (3-term bf16 split)
// 16 stages of K=64: p<8 -> B=xh[koff], A passes {Wh, Wl};  p>=8 -> B=xl[koff], A pass {Wh}.
// Stage = A0 16KB | A1 16KB | B 16KB = 48KB, double-buffered.
#define STG_BYTES 49152
#define GM_SMEM (2 * STG_BYTES)

__global__ __launch_bounds__(256) void gemm_mma() {
    extern __shared__ __align__(128) char smem[];
    const uint32_t sb = smem_u32(smem);
    const int tid = threadIdx.x;
    const int wid = tid >> 5, lane = tid & 31;
    const int n0 = blockIdx.x * 128;       // flattened b*t column base
    const int m0 = blockIdx.y * 128;       // channel base
    const int wm = wid & 1, wn = wid >> 1; // warp tile origin
    const int ml = lane >> 3, rin = lane & 7;

    float acc[4][4][4];
#pragma unroll
    for (int i = 0; i < 4; i++)
#pragma unroll
        for (int j = 0; j < 4; j++)
#pragma unroll
            for (int k = 0; k < 4; k++) acc[i][j][k] = 0.f;

    auto issue = [&](int p) {
        const bool dual = p < 8;
        const int koff = (p & 7) * 64;
        const __nv_bfloat16* bseg = dual ? g_xh : g_xl;
        const uint32_t st = sb + (p & 1) * STG_BYTES;
#pragma unroll
        for (int j = 0; j < 4; j++) {
            int idx = tid + j * 256;
            int r = idx >> 3, cc = idx & 7;
            const uint32_t dsw = SWZ128((uint32_t)(r * 128 + cc * 16));
            CP_ASYNC16(st + dsw, g_Wh + (size_t)(m0 + r) * CC + koff + cc * 8);
            if (dual)
                CP_ASYNC16(st + 16384 + dsw, g_Wl + (size_t)(m0 + r) * CC + koff + cc * 8);
            CP_ASYNC16(st + 32768 + dsw, bseg + (size_t)(n0 + r) * CC + koff + cc * 8);
        }
        asm volatile("cp.async.commit_group;");
    };

    auto compute = [&](uint32_t stA, uint32_t stB) {
#pragma unroll
        for (int ks = 0; ks < 4; ks++) {
            uint32_t a[4][4];
#pragma unroll
            for (int mi = 0; mi < 4; mi++) {
                const int row = wm * 64 + mi * 16 + (ml & 1) * 8 + rin;
                const int kc = 2 * ks + (ml >> 1);
                ldsm_x4(a[mi][0], a[mi][1], a[mi][2], a[mi][3],
                        stA + row * 128 + ((kc ^ (row & 7)) << 4));
            }
            uint32_t bfr[2][4];
#pragma unroll
            for (int bi = 0; bi < 2; bi++) {
                const int n = wn * 32 + bi * 16 + (ml >> 1) * 8 + rin;
                const int kc = 2 * ks + (ml & 1);
                ldsm_x4(bfr[bi][0], bfr[bi][1], bfr[bi][2], bfr[bi][3],
                        stB + n * 128 + ((kc ^ (n & 7)) << 4));
            }
#pragma unroll
            for (int mi = 0; mi < 4; mi++)
#pragma unroll
                for (int ni = 0; ni < 4; ni++)
                    MMA16816(acc[mi][ni], a[mi],
                             bfr[ni >> 1][(ni & 1) * 2], bfr[ni >> 1][(ni & 1) * 2 + 1]);
        }
    };

    issue(0);
#pragma unroll 1
    for (int p = 0; p < PSTG; p++) {
        if (p + 1 < PSTG) {
            issue(p + 1);
            asm volatile("cp.async.wait_group 1;");
        } else {
            asm volatile("cp.async.wait_group 0;");
        }
        __syncthreads();
        const uint32_t st = sb + (p & 1) * STG_BYTES;
        compute(st, st + 32768);              // Wh pass
        if (p < 8) compute(st + 16384, st + 32768);  // Wl pass (same B tile)
        __syncthreads();
    }

    // epilogue: c0,c1 at (row, col..col+1); c2,c3 at (row+8, col..col+1)
    const int b = n0 >> 12;
    const int t0 = n0 & (TT_ - 1);
#pragma unroll
    for (int mi = 0; mi < 4; mi++) {
#pragma unroll
        for (int h = 0; h < 2; h++) {
            const int ch = m0 + wm * 64 + mi * 16 + (lane >> 2) + h * 8;
            if (ch < NCH) {
                float* p = g_proj + ((size_t)b * NCH + ch) * TT_ + t0 + wn * 32 + (lane & 3) * 2;
#pragma unroll
                for (int ni = 0; ni < 4; ni++) {
                    float2 v = make_float2(acc[mi][ni][h * 2], acc[mi][ni][h * 2 + 1]);
                    *(float2*)(p + ni * 8) = v;
                }
            }
        }
    }
}

// ---------------- BN stats phase 1: per-(channel, batch) partial sums ----------------
__global__ __launch_bounds__(256) void bn_part() {
    const int ci = blockIdx.x, bb = blockIdx.y;
    const int ch = ci < 64 ? ci : ci + 16;
    const int tid = threadIdx.x;
    const float* p = g_proj + ((size_t)bb * NCH + ch) * TT_;
    float s = 0.f, s2 = 0.f;
    for (int i = tid * 4; i < TT_; i += 256 * 4) {
        float4 v = *(const float4*)(p + i);
        s += v.x + v.y + v.z + v.w;
        s2 += v.x * v.x + v.y * v.y + v.z * v.z + v.w * v.w;
    }
#pragma unroll
    for (int o = 16; o > 0; o >>= 1) {
        s  += __shfl_down_sync(0xffffffffu, s, o);
        s2 += __shfl_down_sync(0xffffffffu, s2, o);
    }
    __shared__ float ws[8], ws2[8];
    if ((tid & 31) == 0) { ws[tid >> 5] = s; ws2[tid >> 5] = s2; }
    __syncthreads();
    if (tid == 0) {
        float t = 0.f, t2 = 0.f;
#pragma unroll
        for (int w = 0; w < 8; w++) { t += ws[w]; t2 += ws2[w]; }
        g_bnp[(ci * 8 + bb) * 2]     = t;
        g_bnp[(ci * 8 + bb) * 2 + 1] = t2;
    }
}

// ---------------- BN stats phase 2: fold to per-channel affine ----------------
__global__ void bn_final(const float* __restrict__ gq, const float* __restrict__ bq,
                         const float* __restrict__ gv, const float* __restrict__ bv) {
    const int ci = threadIdx.x;
    if (ci >= 192) return;
    float s = 0.f, s2 = 0.f;
#pragma unroll
    for (int bb = 0; bb < 8; bb++) {
        s  += g_bnp[(ci * 8 + bb) * 2];
        s2 += g_bnp[(ci * 8 + bb) * 2 + 1];
    }
    const float N = (float)(BB * TT_);
    float mean = s / N;
    float var = s2 / N - mean * mean;
    float g = ci < 64 ? gq[ci] : gv[ci - 64];
    float be = ci < 64 ? bq[ci] : bv[ci - 64];
    float sc = g * rsqrtf(var + 1e-5f);
    g_scale[ci] = sc;
    g_shift[ci] = be - mean * sc;
}

// ---------------- softmax over t for k rows (in place) ----------------
__global__ __launch_bounds__(256) void softmax_k() {
    const int b = blockIdx.y, k = blockIdx.x;
    float* row = g_proj + ((size_t)b * NCH + 64 + k) * TT_;
    __shared__ float buf[TT_];
    __shared__ float red[256];
    const int tid = threadIdx.x;
    float m = -1e30f;
    for (int i = tid; i < TT_; i += 256) { float v = row[i]; buf[i] = v; m = fmaxf(m, v); }
    red[tid] = m; __syncthreads();
    for (int o = 128; o > 0; o >>= 1) { if (tid < o) red[tid] = fmaxf(red[tid], red[tid + o]); __syncthreads(); }
    m = red[0]; __syncthreads();
    float s = 0.f;
    for (int i = tid; i < TT_; i += 256) { float e = expf(buf[i] - m); buf[i] = e; s += e; }
    red[tid] = s; __syncthreads();
    for (int o = 128; o > 0; o >>= 1) { if (tid < o) red[tid] += red[tid + o]; __syncthreads(); }
    const float inv = 1.f / red[0];
    for (int i = tid; i < TT_; i += 256) row[i] = buf[i] * inv;
}

// ---------------- lambda_c partials ----------------
__global__ __launch_bounds__(256) void lamc_part() {
    const int b = blockIdx.y, chunk = blockIdx.x;
    const int t0 = chunk * 128;
    const float* pk = g_proj + ((size_t)b * NCH + 64) * TT_ + t0;
    const float* pv = g_proj + ((size_t)b * NCH + 80) * TT_ + t0;
    __shared__ float sk[KK][33];
    __shared__ float svt[32][132];
    const int tid = threadIdx.x;
    const int k = tid & 15, vg = tid >> 4;
    float acc[8];
#pragma unroll
    for (int j = 0; j < 8; j++) acc[j] = 0.f;

#pragma unroll 1
    for (int sub = 0; sub < 4; sub++) {
        for (int i = tid; i < KK * 32; i += 256) {
            int kk = i >> 5, tt = i & 31;
            sk[kk][tt] = pk[(size_t)kk * TT_ + sub * 32 + tt];
        }
        for (int i = tid; i < NV * 32; i += 256) {
            int v = i >> 5, tt = i & 31;
            svt[tt][v] = pv[(size_t)v * TT_ + sub * 32 + tt];
        }
        __syncthreads();
#pragma unroll
        for (int t = 0; t < 32; t++) {
            const float a = sk[k][t];
            const float4 v0 = *(const float4*)&svt[t][vg * 8];
            const float4 v1 = *(const float4*)&svt[t][vg * 8 + 4];
            acc[0] += a * v0.x; acc[1] += a * v0.y; acc[2] += a * v0.z; acc[3] += a * v0.w;
            acc[4] += a * v1.x; acc[5] += a * v1.y; acc[6] += a * v1.z; acc[7] += a * v1.w;
        }
        __syncthreads();
    }
    float* pp = g_part + (((size_t)b * 32 + chunk) * KK + k) * VV + vg * 8;
#pragma unroll
    for (int j = 0; j < 8; j++) pp[j] = acc[j];
}

// ---------------- reduce partials + fold v BN affine ----------------
__global__ void lamc_reduce() {
    const int i = blockIdx.x * 256 + threadIdx.x;
    if (i >= BB * KK * VV) return;
    const int v = i & 127;
    const int b = i >> 11;
    const float* p = g_part + (size_t)b * 32 * KK * VV + (i & 2047);
    float s = 0.f;
#pragma unroll 1
    for (int c = 0; c < 32; c++) s += p[(size_t)c * KK * VV];
    g_lambda[i] = g_scale[64 + v] * s + g_shift[64 + v];
}

// ---------------- fused output ----------------
#define M_TT 128
#define M_HW 144

__global__ __launch_bounds__(256) void lambda_main(const float* __restrict__ pos_w,
                                                   const float* __restrict__ pos_b,
                                                   float* __restrict__ out) {
    extern __shared__ float sm[];
    float* sq  = sm;
    float* sv  = sm + NQ * M_TT;
    float* slc = sv + NV * M_HW;
    float* spw = slc + KK * VV;
    float* spb = spw + KK * RR;

    const int b = blockIdx.y;
    const int t0 = blockIdx.x * M_TT;
    const int tid = threadIdx.x;
    const float* pq = g_proj + (size_t)b * NCH * TT_;
    const float* pv = pq + (size_t)80 * TT_;

    for (int i = tid; i < NQ * M_TT; i += 256) {
        int ch = i >> 7, t = i & 127;
        sq[i] = pq[(size_t)ch * TT_ + t0 + t] * g_scale[ch] + g_shift[ch];
    }
    for (int i = tid; i < NV * M_HW; i += 256) {
        int v = i / M_HW, tr = i % M_HW;
        float val = 0.f;
        if (tr < M_TT + RR - 1) {
            int tg = t0 - (RR / 2) + tr;
            if (tg >= 0 && tg < TT_)
                val = pv[(size_t)v * TT_ + tg] * g_scale[64 + v] + g_shift[64 + v];
        }
        sv[i] = val;
    }
    for (int i = tid; i < KK * VV; i += 256) slc[i] = g_lambda[(size_t)b * KK * VV + i];
    if (tid < KK * RR) spw[tid] = pos_w[tid];
    if (tid < KK) spb[tid] = pos_b[tid];
    __syncthreads();

    const int t = tid & 127;
    const int vh = tid >> 7;

    float q[NQ];
#pragma unroll
    for (int ch = 0; ch < NQ; ch++) q[ch] = sq[ch * M_TT + t];

    float qw[HH][RR];
    float qb[HH] = {0.f, 0.f, 0.f, 0.f};
#pragma unroll
    for (int h = 0; h < HH; h++)
#pragma unroll
        for (int r = 0; r < RR; r++) qw[h][r] = 0.f;

#pragma unroll
    for (int k = 0; k < KK; k++) {
        const float pb = spb[k];
#pragma unroll
        for (int h = 0; h < HH; h++) qb[h] += q[h * KK + k] * pb;
#pragma unroll
        for (int r = 0; r < RR; r++) {
            const float w = spw[k * RR + r];
#pragma unroll
            for (int h = 0; h < HH; h++) qw[h][r] += q[h * KK + k] * w;
        }
    }

    float* ob = out + (size_t)b * 512 * TT_ + t0 + t;
#pragma unroll 2
    for (int v = 0; v < 64; v++) {
        const int vv = vh * 64 + v;
        float a0 = qb[0], a1 = qb[1], a2 = qb[2], a3 = qb[3];
#pragma unroll
        for (int k = 0; k < KK; k++) {
            const float l = slc[k * VV + vv];
            a0 += q[k] * l;
            a1 += q[KK + k] * l;
            a2 += q[2 * KK + k] * l;
            a3 += q[3 * KK + k] * l;
        }
        const float* vp = sv + vv * M_HW + t;
#pragma unroll
        for (int r = 0; r < RR; r++) {
            const float x = vp[r];
            a0 += qw[0][r] * x;
            a1 += qw[1][r] * x;
            a2 += qw[2][r] * x;
            a3 += qw[3][r] * x;
        }
        ob[(size_t)(0 * VV + vv) * TT_] = a0;
        ob[(size_t)(1 * VV + vv) * TT_] = a1;
        ob[(size_t)(2 * VV + vv) * TT_] = a2;
        ob[(size_t)(3 * VV + vv) * TT_] = a3;
    }
}

// ---------------- launch ----------------
extern "C" void kernel_launch(void* const* d_in, const int* in_sizes, int n_in,
                              void* d_out, int out_size) {
    const float* x  = (const float*)d_in[0];
    const float* Wq = (const float*)d_in[1];
    const float* Wk = (const float*)d_in[2];
    const float* Wv = (const float*)d_in[3];
    const float* gq = (const float*)d_in[4];
    const float* bq = (const float*)d_in[5];
    const float* gv = (const float*)d_in[6];
    const float* bv = (const float*)d_in[7];
    const float* pw = (const float*)d_in[8];
    const float* pb = (const float*)d_in[9];
    float* out = (float*)d_out;

    const size_t main_smem = (size_t)(NQ * M_TT + NV * M_HW + KK * VV + KK * RR + KK) * sizeof(float);
    cudaFuncSetAttribute(lambda_main, cudaFuncAttributeMaxDynamicSharedMemorySize, (int)main_smem);
    cudaFuncSetAttribute(gemm_mma, cudaFuncAttributeMaxDynamicSharedMemorySize, GM_SMEM);

    // gemm_mma is deliberately the 4th launch (ncu capture slot)
    xsplit<<<dim3(TT_ / 32, CC / 32, 4), 256>>>(x, 0);
    xsplit<<<dim3(TT_ / 32, CC / 32, 4), 256>>>(x, 4);
    pack_w_split<<<(MPAD * CC + 255) / 256, 256>>>(Wq, Wk, Wv);
    gemm_mma<<<dim3(NT / 128, 2), 256, GM_SMEM>>>();
    bn_part<<<dim3(192, 8), 256>>>();
    bn_final<<<1, 192>>>(gq, bq, gv, bv);
    softmax_k<<<dim3(KK, BB), 256>>>();
    lamc_part<<<dim3(32, BB), 256>>>();
    lamc_reduce<<<(BB * KK * VV + 255) / 256, 256>>>();
    lambda_main<<<dim3(TT_ / M_TT, BB), 256, main_smem>>>(pw, pb, out);
}

// round 11
// speedup vs baseline: 1.5354x; 1.0304x over previous
#include <cuda_runtime.h>
#include <cuda_bf16.h>
#include <cstdint>
#include <cstddef>

// Problem constants
#define BB   8
#define CC   512
#define TT_  4096
#define HH   4
#define KK   16
#define VV   128
#define RR   15
#define NCH  208          // 64 q + 16 k + 128 v
#define NQ   64
#define NV   128
#define MPAD 256
#define NT   32768        // BB*TT_
#define PSTG 16           // paired stages: 8x (xh: Wh+Wl) + 8x (xl: Wh)

// ---------------- scratch ----------------
__device__ float g_proj[(size_t)BB * NCH * TT_];        // [8][208][4096]
__device__ float g_scale[192];
__device__ float g_shift[192];
__device__ float g_part[(size_t)BB * 32 * KK * VV];
__device__ float g_lambda[(size_t)BB * KK * VV];
__device__ float g_bnp[192 * 8 * 2];
__device__ __nv_bfloat16 g_Wh[MPAD * CC];
__device__ __nv_bfloat16 g_Wl[MPAD * CC];
__device__ __nv_bfloat16 g_xh[(size_t)NT * CC];         // [b*t][c]
__device__ __nv_bfloat16 g_xl[(size_t)NT * CC];

// ---------------- helpers ----------------
__device__ __forceinline__ uint32_t smem_u32(const void* p) {
    uint32_t a;
    asm("{ .reg .u64 t; cvta.to.shared.u64 t, %1; cvt.u32.u64 %0, t; }" : "=r"(a) : "l"(p));
    return a;
}
#define SWZ128(off) ((off) ^ (((off) >> 3) & 0x70))
#define CP_ASYNC16(dst, src) \
    asm volatile("cp.async.cg.shared.global [%0], [%1], 16;" :: "r"(dst), "l"(src))

__device__ __forceinline__ void ldsm_x4(uint32_t& r0, uint32_t& r1, uint32_t& r2, uint32_t& r3,
                                        uint32_t addr) {
    asm volatile("ldmatrix.sync.aligned.m8n8.x4.shared.b16 {%0,%1,%2,%3}, [%4];"
        : "=r"(r0), "=r"(r1), "=r"(r2), "=r"(r3) : "r"(addr));
}
#define MMA16816(c, a, b0, b1) \
    asm volatile("mma.sync.aligned.m16n8k16.row.col.f32.bf16.bf16.f32 " \
        "{%0,%1,%2,%3}, {%4,%5,%6,%7}, {%8,%9}, {%0,%1,%2,%3};" \
        : "+f"((c)[0]), "+f"((c)[1]), "+f"((c)[2]), "+f"((c)[3]) \
        : "r"((a)[0]), "r"((a)[1]), "r"((a)[2]), "r"((a)[3]), "r"(b0), "r"(b1))

// ---------------- pack W, split into bf16 hi/lo (padded to 256 rows) ----------------
__global__ void pack_w_split(const float* __restrict__ Wq, const float* __restrict__ Wk,
                             const float* __restrict__ Wv) {
    int i = blockIdx.x * 256 + threadIdx.x;
    if (i >= MPAD * CC) return;
    int ch = i / CC, c = i % CC;
    float w = 0.f;
    if (ch < 64)       w = Wq[ch * CC + c];
    else if (ch < 80)  w = Wk[(ch - 64) * CC + c];
    else if (ch < NCH) w = Wv[(ch - 80) * CC + c];
    __nv_bfloat16 h = __float2bfloat16(w);
    g_Wh[i] = h;
    g_Wl[i] = __float2bfloat16(w - __bfloat162float(h));
}

// ---------------- transpose + split x v2: [b][c][t] f32 -> [b*t][c] bf16 hi/lo ----------------
// tile 32(t) x 64(c); writes packed bf16x2 -> 128B contiguous per row per array
__global__ __launch_bounds__(256) void xsplit(const float* __restrict__ x, int b0) {
    __shared__ float s[64][33];
    const int b = blockIdx.z + b0, c0 = blockIdx.y * 64, t0 = blockIdx.x * 32;
    const int tid = threadIdx.x;
    const int tx = tid & 31, cy = tid >> 5;   // cy 0..7
    const float* xp = x + ((size_t)b * CC + c0) * TT_ + t0;
#pragma unroll
    for (int j = 0; j < 8; j++)
        s[cy + j * 8][tx] = xp[(size_t)(cy + j * 8) * TT_ + tx];
    __syncthreads();
    const size_t row0 = (size_t)b * TT_ + t0;
    const int lane = tid & 31, w = tid >> 5;
    uint32_t* oh = (uint32_t*)g_xh;
    uint32_t* ol = (uint32_t*)g_xl;
#pragma unroll
    for (int j = 0; j < 4; j++) {
        const int r = w * 4 + j;          // t index in tile
        const float v0 = s[lane * 2][r];
        const float v1 = s[lane * 2 + 1][r];
        __nv_bfloat162 h2 = make_bfloat162(__float2bfloat16(v0), __float2bfloat16(v1));
        __nv_bfloat162 l2 = make_bfloat162(__float2bfloat16(v0 - __bfloat162float(h2.x)),
                                           __float2bfloat16(v1 - __bfloat162float(h2.y)));
        const size_t idx = ((row0 + r) * CC + c0) / 2 + lane;
        oh[idx] = *(uint32_t*)&h2;
        ol[idx] = *(uint32_t*)&l2;
    }
}

// ---------------- mma.sync bf16 projection GEMM (paired stages, fused dual A-pass) ----------------
// D[ch][gt] = Wh.xh + Wl.xh + Wh.xl  (3-term bf16 split)
// 16 stages of K=64: p<8 -> B=xh[koff], A passes {Wh, Wl};  p>=8 -> B=xl[koff], A pass {Wh}.
// Stage = A0 16KB | A1 16KB | B 16KB = 48KB, double-buffered.
#define STG_BYTES 49152
#define GM_SMEM (2 * STG_BYTES)

__global__ __launch_bounds__(256) void gemm_mma() {
    extern __shared__ __align__(128) char smem[];
    const uint32_t sb = smem_u32(smem);
    const int tid = threadIdx.x;
    const int wid = tid >> 5, lane = tid & 31;
    const int n0 = blockIdx.x * 128;       // flattened b*t column base
    const int m0 = blockIdx.y * 128;       // channel base
    const int wm = wid & 1, wn = wid >> 1; // warp tile origin
    const int ml = lane >> 3, rin = lane & 7;

    float acc[4][4][4];
#pragma unroll
    for (int i = 0; i < 4; i++)
#pragma unroll
        for (int j = 0; j < 4; j++)
#pragma unroll
            for (int k = 0; k < 4; k++) acc[i][j][k] = 0.f;

    auto issue = [&](int p) {
        const bool dual = p < 8;
        const int koff = (p & 7) * 64;
        const __nv_bfloat16* bseg = dual ? g_xh : g_xl;
        const uint32_t st = sb + (p & 1) * STG_BYTES;
#pragma unroll
        for (int j = 0; j < 4; j++) {
            int idx = tid + j * 256;
            int r = idx >> 3, cc = idx & 7;
            const uint32_t dsw = SWZ128((uint32_t)(r * 128 + cc * 16));
            CP_ASYNC16(st + dsw, g_Wh + (size_t)(m0 + r) * CC + koff + cc * 8);
            if (dual)
                CP_ASYNC16(st + 16384 + dsw, g_Wl + (size_t)(m0 + r) * CC + koff + cc * 8);
            CP_ASYNC16(st + 32768 + dsw, bseg + (size_t)(n0 + r) * CC + koff + cc * 8);
        }
        asm volatile("cp.async.commit_group;");
    };

    // fused: per ks load B once, run Wh-A MMAs, then (if dual) Wl-A MMAs into same acc
    auto compute_pair = [&](uint32_t stA0, uint32_t stA1, uint32_t stB, bool dual) {
#pragma unroll
        for (int ks = 0; ks < 4; ks++) {
            uint32_t bfr[2][4];
#pragma unroll
            for (int bi = 0; bi < 2; bi++) {
                const int n = wn * 32 + bi * 16 + (ml >> 1) * 8 + rin;
                const int kc = 2 * ks + (ml & 1);
                ldsm_x4(bfr[bi][0], bfr[bi][1], bfr[bi][2], bfr[bi][3],
                        stB + n * 128 + ((kc ^ (n & 7)) << 4));
            }
            uint32_t a[4][4];
#pragma unroll
            for (int mi = 0; mi < 4; mi++) {
                const int row = wm * 64 + mi * 16 + (ml & 1) * 8 + rin;
                const int kc = 2 * ks + (ml >> 1);
                ldsm_x4(a[mi][0], a[mi][1], a[mi][2], a[mi][3],
                        stA0 + row * 128 + ((kc ^ (row & 7)) << 4));
            }
#pragma unroll
            for (int mi = 0; mi < 4; mi++)
#pragma unroll
                for (int ni = 0; ni < 4; ni++)
                    MMA16816(acc[mi][ni], a[mi],
                             bfr[ni >> 1][(ni & 1) * 2], bfr[ni >> 1][(ni & 1) * 2 + 1]);
            if (dual) {
#pragma unroll
                for (int mi = 0; mi < 4; mi++) {
                    const int row = wm * 64 + mi * 16 + (ml & 1) * 8 + rin;
                    const int kc = 2 * ks + (ml >> 1);
                    ldsm_x4(a[mi][0], a[mi][1], a[mi][2], a[mi][3],
                            stA1 + row * 128 + ((kc ^ (row & 7)) << 4));
                }
#pragma unroll
                for (int mi = 0; mi < 4; mi++)
#pragma unroll
                    for (int ni = 0; ni < 4; ni++)
                        MMA16816(acc[mi][ni], a[mi],
                                 bfr[ni >> 1][(ni & 1) * 2], bfr[ni >> 1][(ni & 1) * 2 + 1]);
            }
        }
    };

    issue(0);
#pragma unroll 1
    for (int p = 0; p < PSTG; p++) {
        if (p + 1 < PSTG) {
            issue(p + 1);
            asm volatile("cp.async.wait_group 1;");
        } else {
            asm volatile("cp.async.wait_group 0;");
        }
        __syncthreads();
        const uint32_t st = sb + (p & 1) * STG_BYTES;
        compute_pair(st, st + 16384, st + 32768, p < 8);
        __syncthreads();
    }

    // epilogue: c0,c1 at (row, col..col+1); c2,c3 at (row+8, col..col+1)
    const int b = n0 >> 12;
    const int t0 = n0 & (TT_ - 1);
#pragma unroll
    for (int mi = 0; mi < 4; mi++) {
#pragma unroll
        for (int h = 0; h < 2; h++) {
            const int ch = m0 + wm * 64 + mi * 16 + (lane >> 2) + h * 8;
            if (ch < NCH) {
                float* p = g_proj + ((size_t)b * NCH + ch) * TT_ + t0 + wn * 32 + (lane & 3) * 2;
#pragma unroll
                for (int ni = 0; ni < 4; ni++) {
                    float2 v = make_float2(acc[mi][ni][h * 2], acc[mi][ni][h * 2 + 1]);
                    *(float2*)(p + ni * 8) = v;
                }
            }
        }
    }
}

// ---------------- BN stats phase 1: per-(channel, batch) partial sums ----------------
__global__ __launch_bounds__(256) void bn_part() {
    const int ci = blockIdx.x, bb = blockIdx.y;
    const int ch = ci < 64 ? ci : ci + 16;
    const int tid = threadIdx.x;
    const float* p = g_proj + ((size_t)bb * NCH + ch) * TT_;
    float s = 0.f, s2 = 0.f;
    for (int i = tid * 4; i < TT_; i += 256 * 4) {
        float4 v = *(const float4*)(p + i);
        s += v.x + v.y + v.z + v.w;
        s2 += v.x * v.x + v.y * v.y + v.z * v.z + v.w * v.w;
    }
#pragma unroll
    for (int o = 16; o > 0; o >>= 1) {
        s  += __shfl_down_sync(0xffffffffu, s, o);
        s2 += __shfl_down_sync(0xffffffffu, s2, o);
    }
    __shared__ float ws[8], ws2[8];
    if ((tid & 31) == 0) { ws[tid >> 5] = s; ws2[tid >> 5] = s2; }
    __syncthreads();
    if (tid == 0) {
        float t = 0.f, t2 = 0.f;
#pragma unroll
        for (int w = 0; w < 8; w++) { t += ws[w]; t2 += ws2[w]; }
        g_bnp[(ci * 8 + bb) * 2]     = t;
        g_bnp[(ci * 8 + bb) * 2 + 1] = t2;
    }
}

// ---------------- BN stats phase 2: fold to per-channel affine ----------------
__global__ void bn_final(const float* __restrict__ gq, const float* __restrict__ bq,
                         const float* __restrict__ gv, const float* __restrict__ bv) {
    const int ci = threadIdx.x;
    if (ci >= 192) return;
    float s = 0.f, s2 = 0.f;
#pragma unroll
    for (int bb = 0; bb < 8; bb++) {
        s  += g_bnp[(ci * 8 + bb) * 2];
        s2 += g_bnp[(ci * 8 + bb) * 2 + 1];
    }
    const float N = (float)(BB * TT_);
    float mean = s / N;
    float var = s2 / N - mean * mean;
    float g = ci < 64 ? gq[ci] : gv[ci - 64];
    float be = ci < 64 ? bq[ci] : bv[ci - 64];
    float sc = g * rsqrtf(var + 1e-5f);
    g_scale[ci] = sc;
    g_shift[ci] = be - mean * sc;
}

// ---------------- softmax over t for k rows (in place) ----------------
__global__ __launch_bounds__(256) void softmax_k() {
    const int b = blockIdx.y, k = blockIdx.x;
    float* row = g_proj + ((size_t)b * NCH + 64 + k) * TT_;
    __shared__ float buf[TT_];
    __shared__ float red[256];
    const int tid = threadIdx.x;
    float m = -1e30f;
    for (int i = tid; i < TT_; i += 256) { float v = row[i]; buf[i] = v; m = fmaxf(m, v); }
    red[tid] = m; __syncthreads();
    for (int o = 128; o > 0; o >>= 1) { if (tid < o) red[tid] = fmaxf(red[tid], red[tid + o]); __syncthreads(); }
    m = red[0]; __syncthreads();
    float s = 0.f;
    for (int i = tid; i < TT_; i += 256) { float e = expf(buf[i] - m); buf[i] = e; s += e; }
    red[tid] = s; __syncthreads();
    for (int o = 128; o > 0; o >>= 1) { if (tid < o) red[tid] += red[tid + o]; __syncthreads(); }
    const float inv = 1.f / red[0];
    for (int i = tid; i < TT_; i += 256) row[i] = buf[i] * inv;
}

// ---------------- lambda_c partials ----------------
__global__ __launch_bounds__(256) void lamc_part() {
    const int b = blockIdx.y, chunk = blockIdx.x;
    const int t0 = chunk * 128;
    const float* pk = g_proj + ((size_t)b * NCH + 64) * TT_ + t0;
    const float* pv = g_proj + ((size_t)b * NCH + 80) * TT_ + t0;
    __shared__ float sk[KK][33];
    __shared__ float svt[32][132];
    const int tid = threadIdx.x;
    const int k = tid & 15, vg = tid >> 4;
    float acc[8];
#pragma unroll
    for (int j = 0; j < 8; j++) acc[j] = 0.f;

#pragma unroll 1
    for (int sub = 0; sub < 4; sub++) {
        for (int i = tid; i < KK * 32; i += 256) {
            int kk = i >> 5, tt = i & 31;
            sk[kk][tt] = pk[(size_t)kk * TT_ + sub * 32 + tt];
        }
        for (int i = tid; i < NV * 32; i += 256) {
            int v = i >> 5, tt = i & 31;
            svt[tt][v] = pv[(size_t)v * TT_ + sub * 32 + tt];
        }
        __syncthreads();
#pragma unroll
        for (int t = 0; t < 32; t++) {
            const float a = sk[k][t];
            const float4 v0 = *(const float4*)&svt[t][vg * 8];
            const float4 v1 = *(const float4*)&svt[t][vg * 8 + 4];
            acc[0] += a * v0.x; acc[1] += a * v0.y; acc[2] += a * v0.z; acc[3] += a * v0.w;
            acc[4] += a * v1.x; acc[5] += a * v1.y; acc[6] += a * v1.z; acc[7] += a * v1.w;
        }
        __syncthreads();
    }
    float* pp = g_part + (((size_t)b * 32 + chunk) * KK + k) * VV + vg * 8;
#pragma unroll
    for (int j = 0; j < 8; j++) pp[j] = acc[j];
}

// ---------------- reduce partials + fold v BN affine ----------------
__global__ void lamc_reduce() {
    const int i = blockIdx.x * 256 + threadIdx.x;
    if (i >= BB * KK * VV) return;
    const int v = i & 127;
    const int b = i >> 11;
    const float* p = g_part + (size_t)b * 32 * KK * VV + (i & 2047);
    float s = 0.f;
#pragma unroll 1
    for (int c = 0; c < 32; c++) s += p[(size_t)c * KK * VV];
    g_lambda[i] = g_scale[64 + v] * s + g_shift[64 + v];
}

// ---------------- fused output ----------------
#define M_TT 128
#define M_HW 144

__global__ __launch_bounds__(256) void lambda_main(const float* __restrict__ pos_w,
                                                   const float* __restrict__ pos_b,
                                                   float* __restrict__ out) {
    extern __shared__ float sm[];
    float* sq  = sm;
    float* sv  = sm + NQ * M_TT;
    float* slc = sv + NV * M_HW;
    float* spw = slc + KK * VV;
    float* spb = spw + KK * RR;

    const int b = blockIdx.y;
    const int t0 = blockIdx.x * M_TT;
    const int tid = threadIdx.x;
    const float* pq = g_proj + (size_t)b * NCH * TT_;
    const float* pv = pq + (size_t)80 * TT_;

    for (int i = tid; i < NQ * M_TT; i += 256) {
        int ch = i >> 7, t = i & 127;
        sq[i] = pq[(size_t)ch * TT_ + t0 + t] * g_scale[ch] + g_shift[ch];
    }
    for (int i = tid; i < NV * M_HW; i += 256) {
        int v = i / M_HW, tr = i % M_HW;
        float val = 0.f;
        if (tr < M_TT + RR - 1) {
            int tg = t0 - (RR / 2) + tr;
            if (tg >= 0 && tg < TT_)
                val = pv[(size_t)v * TT_ + tg] * g_scale[64 + v] + g_shift[64 + v];
        }
        sv[i] = val;
    }
    for (int i = tid; i < KK * VV; i += 256) slc[i] = g_lambda[(size_t)b * KK * VV + i];
    if (tid < KK * RR) spw[tid] = pos_w[tid];
    if (tid < KK) spb[tid] = pos_b[tid];
    __syncthreads();

    const int t = tid & 127;
    const int vh = tid >> 7;

    float q[NQ];
#pragma unroll
    for (int ch = 0; ch < NQ; ch++) q[ch] = sq[ch * M_TT + t];

    float qw[HH][RR];
    float qb[HH] = {0.f, 0.f, 0.f, 0.f};
#pragma unroll
    for (int h = 0; h < HH; h++)
#pragma unroll
        for (int r = 0; r < RR; r++) qw[h][r] = 0.f;

#pragma unroll
    for (int k = 0; k < KK; k++) {
        const float pb = spb[k];
#pragma unroll
        for (int h = 0; h < HH; h++) qb[h] += q[h * KK + k] * pb;
#pragma unroll
        for (int r = 0; r < RR; r++) {
            const float w = spw[k * RR + r];
#pragma unroll
            for (int h = 0; h < HH; h++) qw[h][r] += q[h * KK + k] * w;
        }
    }

    float* ob = out + (size_t)b * 512 * TT_ + t0 + t;
#pragma unroll 2
    for (int v = 0; v < 64; v++) {
        const int vv = vh * 64 + v;
        float a0 = qb[0], a1 = qb[1], a2 = qb[2], a3 = qb[3];
#pragma unroll
        for (int k = 0; k < KK; k++) {
            const float l = slc[k * VV + vv];
            a0 += q[k] * l;
            a1 += q[KK + k] * l;
            a2 += q[2 * KK + k] * l;
            a3 += q[3 * KK + k] * l;
        }
        const float* vp = sv + vv * M_HW + t;
#pragma unroll
        for (int r = 0; r < RR; r++) {
            const float x = vp[r];
            a0 += qw[0][r] * x;
            a1 += qw[1][r] * x;
            a2 += qw[2][r] * x;
            a3 += qw[3][r] * x;
        }
        ob[(size_t)(0 * VV + vv) * TT_] = a0;
        ob[(size_t)(1 * VV + vv) * TT_] = a1;
        ob[(size_t)(2 * VV + vv) * TT_] = a2;
        ob[(size_t)(3 * VV + vv) * TT_] = a3;
    }
}

// ---------------- launch ----------------
extern "C" void kernel_launch(void* const* d_in, const int* in_sizes, int n_in,
                              void* d_out, int out_size) {
    const float* x  = (const float*)d_in[0];
    const float* Wq = (const float*)d_in[1];
    const float* Wk = (const float*)d_in[2];
    const float* Wv = (const float*)d_in[3];
    const float* gq = (const float*)d_in[4];
    const float* bq = (const float*)d_in[5];
    const float* gv = (const float*)d_in[6];
    const float* bv = (const float*)d_in[7];
    const float* pw = (const float*)d_in[8];
    const float* pb = (const float*)d_in[9];
    float* out = (float*)d_out;

    const size_t main_smem = (size_t)(NQ * M_TT + NV * M_HW + KK * VV + KK * RR + KK) * sizeof(float);
    cudaFuncSetAttribute(lambda_main, cudaFuncAttributeMaxDynamicSharedMemorySize, (int)main_smem);
    cudaFuncSetAttribute(gemm_mma, cudaFuncAttributeMaxDynamicSharedMemorySize, GM_SMEM);

    // gemm_mma is deliberately the 4th launch (ncu capture slot)
    xsplit<<<dim3(TT_ / 32, CC / 64, 4), 256>>>(x, 0);
    xsplit<<<dim3(TT_ / 32, CC / 64, 4), 256>>>(x, 4);
    pack_w_split<<<(MPAD * CC + 255) / 256, 256>>>(Wq, Wk, Wv);
    gemm_mma<<<dim3(NT / 128, 2), 256, GM_SMEM>>>();
    bn_part<<<dim3(192, 8), 256>>>();
    bn_final<<<1, 192>>>(gq, bq, gv, bv);
    softmax_k<<<dim3(KK, BB), 256>>>();
    lamc_part<<<dim3(32, BB), 256>>>();
    lamc_reduce<<<(BB * KK * VV + 255) / 256, 256>>>();
    lambda_main<<<dim3(TT_ / M_TT, BB), 256, main_smem>>>(pw, pb, out);
}

// round 12
// speedup vs baseline: 1.5631x; 1.0180x over previous
#include <cuda_runtime.h>
#include <cuda_bf16.h>
#include <cstdint>
#include <cstddef>

// Problem constants
#define BB   8
#define CC   512
#define TT_  4096
#define HH   4
#define KK   16
#define VV   128
#define RR   15
#define NCH  208          // 64 q + 16 k + 128 v
#define NQ   64
#define NV   128
#define MPAD 256
#define NT   32768        // BB*TT_
#define PSTG 16           // paired stages: 8x (xh: Wh+Wl) + 8x (xl: Wh)

// ---------------- scratch ----------------
__device__ float g_proj[(size_t)BB * NCH * TT_];        // [8][208][4096]
__device__ float g_scale[192];
__device__ float g_shift[192];
__device__ float g_part[(size_t)BB * 32 * KK * VV];
__device__ float g_lambda[(size_t)BB * KK * VV];
__device__ float g_bnp[192 * 8 * 2];
__device__ float g_kstat[BB * KK * 2];                  // per (b,k): max, 1/sumexp
__device__ __nv_bfloat16 g_Wh[MPAD * CC];
__device__ __nv_bfloat16 g_Wl[MPAD * CC];
__device__ __nv_bfloat16 g_xh[(size_t)NT * CC];         // [b*t][c]
__device__ __nv_bfloat16 g_xl[(size_t)NT * CC];

// ---------------- helpers ----------------
__device__ __forceinline__ uint32_t smem_u32(const void* p) {
    uint32_t a;
    asm("{ .reg .u64 t; cvta.to.shared.u64 t, %1; cvt.u32.u64 %0, t; }" : "=r"(a) : "l"(p));
    return a;
}
#define SWZ128(off) ((off) ^ (((off) >> 3) & 0x70))
#define CP_ASYNC16(dst, src) \
    asm volatile("cp.async.cg.shared.global [%0], [%1], 16;" :: "r"(dst), "l"(src))

__device__ __forceinline__ void ldsm_x4(uint32_t& r0, uint32_t& r1, uint32_t& r2, uint32_t& r3,
                                        uint32_t addr) {
    asm volatile("ldmatrix.sync.aligned.m8n8.x4.shared.b16 {%0,%1,%2,%3}, [%4];"
        : "=r"(r0), "=r"(r1), "=r"(r2), "=r"(r3) : "r"(addr));
}
#define MMA16816(c, a, b0, b1) \
    asm volatile("mma.sync.aligned.m16n8k16.row.col.f32.bf16.bf16.f32 " \
        "{%0,%1,%2,%3}, {%4,%5,%6,%7}, {%8,%9}, {%0,%1,%2,%3};" \
        : "+f"((c)[0]), "+f"((c)[1]), "+f"((c)[2]), "+f"((c)[3]) \
        : "r"((a)[0]), "r"((a)[1]), "r"((a)[2]), "r"((a)[3]), "r"(b0), "r"(b1))

// ---------------- pack W, split into bf16 hi/lo (padded to 256 rows) ----------------
__global__ void pack_w_split(const float* __restrict__ Wq, const float* __restrict__ Wk,
                             const float* __restrict__ Wv) {
    int i = blockIdx.x * 256 + threadIdx.x;
    if (i >= MPAD * CC) return;
    int ch = i / CC, c = i % CC;
    float w = 0.f;
    if (ch < 64)       w = Wq[ch * CC + c];
    else if (ch < 80)  w = Wk[(ch - 64) * CC + c];
    else if (ch < NCH) w = Wv[(ch - 80) * CC + c];
    __nv_bfloat16 h = __float2bfloat16(w);
    g_Wh[i] = h;
    g_Wl[i] = __float2bfloat16(w - __bfloat162float(h));
}

// ---------------- transpose + split x: [b][c][t] f32 -> [b*t][c] bf16 hi/lo ----------------
__global__ __launch_bounds__(256) void xsplit(const float* __restrict__ x, int b0) {
    __shared__ float s[64][33];
    const int b = blockIdx.z + b0, c0 = blockIdx.y * 64, t0 = blockIdx.x * 32;
    const int tid = threadIdx.x;
    const int tx = tid & 31, cy = tid >> 5;   // cy 0..7
    const float* xp = x + ((size_t)b * CC + c0) * TT_ + t0;
#pragma unroll
    for (int j = 0; j < 8; j++)
        s[cy + j * 8][tx] = xp[(size_t)(cy + j * 8) * TT_ + tx];
    __syncthreads();
    const size_t row0 = (size_t)b * TT_ + t0;
    const int lane = tid & 31, w = tid >> 5;
    uint32_t* oh = (uint32_t*)g_xh;
    uint32_t* ol = (uint32_t*)g_xl;
#pragma unroll
    for (int j = 0; j < 4; j++) {
        const int r = w * 4 + j;          // t index in tile
        const float v0 = s[lane * 2][r];
        const float v1 = s[lane * 2 + 1][r];
        __nv_bfloat162 h2 = make_bfloat162(__float2bfloat16(v0), __float2bfloat16(v1));
        __nv_bfloat162 l2 = make_bfloat162(__float2bfloat16(v0 - __bfloat162float(h2.x)),
                                           __float2bfloat16(v1 - __bfloat162float(h2.y)));
        const size_t idx = ((row0 + r) * CC + c0) / 2 + lane;
        oh[idx] = *(uint32_t*)&h2;
        ol[idx] = *(uint32_t*)&l2;
    }
}

// ---------------- mma.sync bf16 projection GEMM (wide tiles) ----------------
// D[ch][gt] = Wh.xh + Wl.xh + Wh.xl
// CTA 128(m) x 256(n), 8 warps (2M x 4N), warp 64x64.
// Stage = A0 16KB | A1 16KB | B 32KB = 64KB, double-buffered (128KB).
#define STG_BYTES 65536
#define GM_SMEM (2 * STG_BYTES)

__global__ __launch_bounds__(256, 1) void gemm_mma() {
    extern __shared__ __align__(128) char smem[];
    const uint32_t sb = smem_u32(smem);
    const int tid = threadIdx.x;
    const int wid = tid >> 5, lane = tid & 31;
    const int n0 = blockIdx.x * 256;       // flattened b*t column base
    const int m0 = blockIdx.y * 128;       // channel base
    const int wm = wid & 1, wn = wid >> 1; // warp tile origin (m:2, n:4)
    const int ml = lane >> 3, rin = lane & 7;

    float acc[4][8][4];
#pragma unroll
    for (int i = 0; i < 4; i++)
#pragma unroll
        for (int j = 0; j < 8; j++)
#pragma unroll
            for (int k = 0; k < 4; k++) acc[i][j][k] = 0.f;

    auto issue = [&](int p) {
        const bool dual = p < 8;
        const int koff = (p & 7) * 64;
        const __nv_bfloat16* bseg = dual ? g_xh : g_xl;
        const uint32_t st = sb + (p & 1) * STG_BYTES;
#pragma unroll
        for (int j = 0; j < 4; j++) {
            int idx = tid + j * 256;
            int r = idx >> 3, cc = idx & 7;
            const uint32_t dsw = SWZ128((uint32_t)(r * 128 + cc * 16));
            CP_ASYNC16(st + dsw, g_Wh + (size_t)(m0 + r) * CC + koff + cc * 8);
            if (dual)
                CP_ASYNC16(st + 16384 + dsw, g_Wl + (size_t)(m0 + r) * CC + koff + cc * 8);
        }
#pragma unroll
        for (int j = 0; j < 8; j++) {
            int idx = tid + j * 256;
            int r = idx >> 3, cc = idx & 7;       // r 0..255
            const uint32_t dsw = SWZ128((uint32_t)(r * 128 + cc * 16));
            CP_ASYNC16(st + 32768 + dsw, bseg + (size_t)(n0 + r) * CC + koff + cc * 8);
        }
        asm volatile("cp.async.commit_group;");
    };

    auto compute_pair = [&](uint32_t stA0, uint32_t stA1, uint32_t stB, bool dual) {
#pragma unroll
        for (int ks = 0; ks < 4; ks++) {
            uint32_t bfr[4][4];
#pragma unroll
            for (int bi = 0; bi < 4; bi++) {
                const int n = wn * 64 + bi * 16 + (ml >> 1) * 8 + rin;
                const int kc = 2 * ks + (ml & 1);
                ldsm_x4(bfr[bi][0], bfr[bi][1], bfr[bi][2], bfr[bi][3],
                        stB + n * 128 + ((kc ^ (n & 7)) << 4));
            }
            uint32_t a[4][4];
#pragma unroll
            for (int mi = 0; mi < 4; mi++) {
                const int row = wm * 64 + mi * 16 + (ml & 1) * 8 + rin;
                const int kc = 2 * ks + (ml >> 1);
                ldsm_x4(a[mi][0], a[mi][1], a[mi][2], a[mi][3],
                        stA0 + row * 128 + ((kc ^ (row & 7)) << 4));
            }
#pragma unroll
            for (int mi = 0; mi < 4; mi++)
#pragma unroll
                for (int ni = 0; ni < 8; ni++)
                    MMA16816(acc[mi][ni], a[mi],
                             bfr[ni >> 1][(ni & 1) * 2], bfr[ni >> 1][(ni & 1) * 2 + 1]);
            if (dual) {
#pragma unroll
                for (int mi = 0; mi < 4; mi++) {
                    const int row = wm * 64 + mi * 16 + (ml & 1) * 8 + rin;
                    const int kc = 2 * ks + (ml >> 1);
                    ldsm_x4(a[mi][0], a[mi][1], a[mi][2], a[mi][3],
                            stA1 + row * 128 + ((kc ^ (row & 7)) << 4));
                }
#pragma unroll
                for (int mi = 0; mi < 4; mi++)
#pragma unroll
                    for (int ni = 0; ni < 8; ni++)
                        MMA16816(acc[mi][ni], a[mi],
                                 bfr[ni >> 1][(ni & 1) * 2], bfr[ni >> 1][(ni & 1) * 2 + 1]);
            }
        }
    };

    issue(0);
#pragma unroll 1
    for (int p = 0; p < PSTG; p++) {
        if (p + 1 < PSTG) {
            issue(p + 1);
            asm volatile("cp.async.wait_group 1;");
        } else {
            asm volatile("cp.async.wait_group 0;");
        }
        __syncthreads();
        const uint32_t st = sb + (p & 1) * STG_BYTES;
        compute_pair(st, st + 16384, st + 32768, p < 8);
        __syncthreads();
    }

    // epilogue
    const int b = n0 >> 12;
    const int t0 = n0 & (TT_ - 1);
#pragma unroll
    for (int mi = 0; mi < 4; mi++) {
#pragma unroll
        for (int h = 0; h < 2; h++) {
            const int ch = m0 + wm * 64 + mi * 16 + (lane >> 2) + h * 8;
            if (ch < NCH) {
                float* p = g_proj + ((size_t)b * NCH + ch) * TT_ + t0 + wn * 64 + (lane & 3) * 2;
#pragma unroll
                for (int ni = 0; ni < 8; ni++) {
                    float2 v = make_float2(acc[mi][ni][h * 2], acc[mi][ni][h * 2 + 1]);
                    *(float2*)(p + ni * 8) = v;
                }
            }
        }
    }
}

// ---------------- BN stats phase 1: per-(channel, batch) partial sums ----------------
__global__ __launch_bounds__(256) void bn_part() {
    const int ci = blockIdx.x, bb = blockIdx.y;
    const int ch = ci < 64 ? ci : ci + 16;
    const int tid = threadIdx.x;
    const float* p = g_proj + ((size_t)bb * NCH + ch) * TT_;
    float s = 0.f, s2 = 0.f;
    for (int i = tid * 4; i < TT_; i += 256 * 4) {
        float4 v = *(const float4*)(p + i);
        s += v.x + v.y + v.z + v.w;
        s2 += v.x * v.x + v.y * v.y + v.z * v.z + v.w * v.w;
    }
#pragma unroll
    for (int o = 16; o > 0; o >>= 1) {
        s  += __shfl_down_sync(0xffffffffu, s, o);
        s2 += __shfl_down_sync(0xffffffffu, s2, o);
    }
    __shared__ float ws[8], ws2[8];
    if ((tid & 31) == 0) { ws[tid >> 5] = s; ws2[tid >> 5] = s2; }
    __syncthreads();
    if (tid == 0) {
        float t = 0.f, t2 = 0.f;
#pragma unroll
        for (int w = 0; w < 8; w++) { t += ws[w]; t2 += ws2[w]; }
        g_bnp[(ci * 8 + bb) * 2]     = t;
        g_bnp[(ci * 8 + bb) * 2 + 1] = t2;
    }
}

// ---------------- BN stats phase 2: fold to per-channel affine ----------------
__global__ void bn_final(const float* __restrict__ gq, const float* __restrict__ bq,
                         const float* __restrict__ gv, const float* __restrict__ bv) {
    const int ci = threadIdx.x;
    if (ci >= 192) return;
    float s = 0.f, s2 = 0.f;
#pragma unroll
    for (int bb = 0; bb < 8; bb++) {
        s  += g_bnp[(ci * 8 + bb) * 2];
        s2 += g_bnp[(ci * 8 + bb) * 2 + 1];
    }
    const float N = (float)(BB * TT_);
    float mean = s / N;
    float var = s2 / N - mean * mean;
    float g = ci < 64 ? gq[ci] : gv[ci - 64];
    float be = ci < 64 ? bq[ci] : bv[ci - 64];
    float sc = g * rsqrtf(var + 1e-5f);
    g_scale[ci] = sc;
    g_shift[ci] = be - mean * sc;
}

// ---------------- k softmax stats: per (b,k) row max and 1/sumexp ----------------
__global__ __launch_bounds__(256) void k_stats() {
    const int b = blockIdx.y, k = blockIdx.x;
    const float* row = g_proj + ((size_t)b * NCH + 64 + k) * TT_;
    const int tid = threadIdx.x;
    float m = -1e30f;
    for (int i = tid * 4; i < TT_; i += 1024) {
        float4 v = *(const float4*)(row + i);
        m = fmaxf(m, fmaxf(fmaxf(v.x, v.y), fmaxf(v.z, v.w)));
    }
#pragma unroll
    for (int o = 16; o > 0; o >>= 1) m = fmaxf(m, __shfl_xor_sync(0xffffffffu, m, o));
    __shared__ float wm[8];
    if ((tid & 31) == 0) wm[tid >> 5] = m;
    __syncthreads();
    m = fmaxf(fmaxf(fmaxf(wm[0], wm[1]), fmaxf(wm[2], wm[3])),
              fmaxf(fmaxf(wm[4], wm[5]), fmaxf(wm[6], wm[7])));
    float s = 0.f;
    for (int i = tid * 4; i < TT_; i += 1024) {
        float4 v = *(const float4*)(row + i);
        s += expf(v.x - m) + expf(v.y - m) + expf(v.z - m) + expf(v.w - m);
    }
#pragma unroll
    for (int o = 16; o > 0; o >>= 1) s += __shfl_xor_sync(0xffffffffu, s, o);
    __shared__ float wsum[8];
    if ((tid & 31) == 0) wsum[tid >> 5] = s;
    __syncthreads();
    if (tid == 0) {
        float t = 0.f;
#pragma unroll
        for (int w = 0; w < 8; w++) t += wsum[w];
        g_kstat[(b * KK + k) * 2]     = m;
        g_kstat[(b * KK + k) * 2 + 1] = 1.f / t;
    }
}

// ---------------- lambda_c partials (softmax applied inline) ----------------
__global__ __launch_bounds__(256) void lamc_part() {
    const int b = blockIdx.y, chunk = blockIdx.x;
    const int t0 = chunk * 128;
    const float* pk = g_proj + ((size_t)b * NCH + 64) * TT_ + t0;
    const float* pv = g_proj + ((size_t)b * NCH + 80) * TT_ + t0;
    __shared__ float sk[KK][33];
    __shared__ float svt[32][132];
    __shared__ float skm[KK], ski[KK];
    const int tid = threadIdx.x;
    const int k = tid & 15, vg = tid >> 4;
    if (tid < KK) {
        skm[tid] = g_kstat[(b * KK + tid) * 2];
        ski[tid] = g_kstat[(b * KK + tid) * 2 + 1];
    }
    __syncthreads();
    float acc[8];
#pragma unroll
    for (int j = 0; j < 8; j++) acc[j] = 0.f;

#pragma unroll 1
    for (int sub = 0; sub < 4; sub++) {
        for (int i = tid; i < KK * 32; i += 256) {
            int kk = i >> 5, tt = i & 31;
            float raw = pk[(size_t)kk * TT_ + sub * 32 + tt];
            sk[kk][tt] = expf(raw - skm[kk]) * ski[kk];
        }
        for (int i = tid; i < NV * 32; i += 256) {
            int v = i >> 5, tt = i & 31;
            svt[tt][v] = pv[(size_t)v * TT_ + sub * 32 + tt];
        }
        __syncthreads();
#pragma unroll
        for (int t = 0; t < 32; t++) {
            const float a = sk[k][t];
            const float4 v0 = *(const float4*)&svt[t][vg * 8];
            const float4 v1 = *(const float4*)&svt[t][vg * 8 + 4];
            acc[0] += a * v0.x; acc[1] += a * v0.y; acc[2] += a * v0.z; acc[3] += a * v0.w;
            acc[4] += a * v1.x; acc[5] += a * v1.y; acc[6] += a * v1.z; acc[7] += a * v1.w;
        }
        __syncthreads();
    }
    float* pp = g_part + (((size_t)b * 32 + chunk) * KK + k) * VV + vg * 8;
#pragma unroll
    for (int j = 0; j < 8; j++) pp[j] = acc[j];
}

// ---------------- reduce partials + fold v BN affine ----------------
__global__ void lamc_reduce() {
    const int i = blockIdx.x * 256 + threadIdx.x;
    if (i >= BB * KK * VV) return;
    const int v = i & 127;
    const int b = i >> 11;
    const float* p = g_part + (size_t)b * 32 * KK * VV + (i & 2047);
    float s = 0.f;
#pragma unroll 1
    for (int c = 0; c < 32; c++) s += p[(size_t)c * KK * VV];
    g_lambda[i] = g_scale[64 + v] * s + g_shift[64 + v];
}

// ---------------- fused output ----------------
#define M_TT 128
#define M_HW 144

__global__ __launch_bounds__(256) void lambda_main(const float* __restrict__ pos_w,
                                                   const float* __restrict__ pos_b,
                                                   float* __restrict__ out) {
    extern __shared__ float sm[];
    float* sq  = sm;
    float* sv  = sm + NQ * M_TT;
    float* slc = sv + NV * M_HW;
    float* spw = slc + KK * VV;
    float* spb = spw + KK * RR;

    const int b = blockIdx.y;
    const int t0 = blockIdx.x * M_TT;
    const int tid = threadIdx.x;
    const float* pq = g_proj + (size_t)b * NCH * TT_;
    const float* pv = pq + (size_t)80 * TT_;

    for (int i = tid; i < NQ * M_TT; i += 256) {
        int ch = i >> 7, t = i & 127;
        sq[i] = pq[(size_t)ch * TT_ + t0 + t] * g_scale[ch] + g_shift[ch];
    }
    for (int i = tid; i < NV * M_HW; i += 256) {
        int v = i / M_HW, tr = i % M_HW;
        float val = 0.f;
        if (tr < M_TT + RR - 1) {
            int tg = t0 - (RR / 2) + tr;
            if (tg >= 0 && tg < TT_)
                val = pv[(size_t)v * TT_ + tg] * g_scale[64 + v] + g_shift[64 + v];
        }
        sv[i] = val;
    }
    for (int i = tid; i < KK * VV; i += 256) slc[i] = g_lambda[(size_t)b * KK * VV + i];
    if (tid < KK * RR) spw[tid] = pos_w[tid];
    if (tid < KK) spb[tid] = pos_b[tid];
    __syncthreads();

    const int t = tid & 127;
    const int vh = tid >> 7;

    float q[NQ];
#pragma unroll
    for (int ch = 0; ch < NQ; ch++) q[ch] = sq[ch * M_TT + t];

    float qw[HH][RR];
    float qb[HH] = {0.f, 0.f, 0.f, 0.f};
#pragma unroll
    for (int h = 0; h < HH; h++)
#pragma unroll
        for (int r = 0; r < RR; r++) qw[h][r] = 0.f;

#pragma unroll
    for (int k = 0; k < KK; k++) {
        const float pb = spb[k];
#pragma unroll
        for (int h = 0; h < HH; h++) qb[h] += q[h * KK + k] * pb;
#pragma unroll
        for (int r = 0; r < RR; r++) {
            const float w = spw[k * RR + r];
#pragma unroll
            for (int h = 0; h < HH; h++) qw[h][r] += q[h * KK + k] * w;
        }
    }

    float* ob = out + (size_t)b * 512 * TT_ + t0 + t;
#pragma unroll 2
    for (int v = 0; v < 64; v++) {
        const int vv = vh * 64 + v;
        float a0 = qb[0], a1 = qb[1], a2 = qb[2], a3 = qb[3];
#pragma unroll
        for (int k = 0; k < KK; k++) {
            const float l = slc[k * VV + vv];
            a0 += q[k] * l;
            a1 += q[KK + k] * l;
            a2 += q[2 * KK + k] * l;
            a3 += q[3 * KK + k] * l;
        }
        const float* vp = sv + vv * M_HW + t;
#pragma unroll
        for (int r = 0; r < RR; r++) {
            const float x = vp[r];
            a0 += qw[0][r] * x;
            a1 += qw[1][r] * x;
            a2 += qw[2][r] * x;
            a3 += qw[3][r] * x;
        }
        ob[(size_t)(0 * VV + vv) * TT_] = a0;
        ob[(size_t)(1 * VV + vv) * TT_] = a1;
        ob[(size_t)(2 * VV + vv) * TT_] = a2;
        ob[(size_t)(3 * VV + vv) * TT_] = a3;
    }
}

// ---------------- launch ----------------
extern "C" void kernel_launch(void* const* d_in, const int* in_sizes, int n_in,
                              void* d_out, int out_size) {
    const float* x  = (const float*)d_in[0];
    const float* Wq = (const float*)d_in[1];
    const float* Wk = (const float*)d_in[2];
    const float* Wv = (const float*)d_in[3];
    const float* gq = (const float*)d_in[4];
    const float* bq = (const float*)d_in[5];
    const float* gv = (const float*)d_in[6];
    const float* bv = (const float*)d_in[7];
    const float* pw = (const float*)d_in[8];
    const float* pb = (const float*)d_in[9];
    float* out = (float*)d_out;

    const size_t main_smem = (size_t)(NQ * M_TT + NV * M_HW + KK * VV + KK * RR + KK) * sizeof(float);
    cudaFuncSetAttribute(lambda_main, cudaFuncAttributeMaxDynamicSharedMemorySize, (int)main_smem);
    cudaFuncSetAttribute(gemm_mma, cudaFuncAttributeMaxDynamicSharedMemorySize, GM_SMEM);

    // gemm_mma is deliberately the 4th launch (ncu capture slot)
    xsplit<<<dim3(TT_ / 32, CC / 64, 4), 256>>>(x, 0);
    xsplit<<<dim3(TT_ / 32, CC / 64, 4), 256>>>(x, 4);
    pack_w_split<<<(MPAD * CC + 255) / 256, 256>>>(Wq, Wk, Wv);
    gemm_mma<<<dim3(NT / 256, 2), 256, GM_SMEM>>>();
    bn_part<<<dim3(192, 8), 256>>>();
    bn_final<<<1, 192>>>(gq, bq, gv, bv);
    k_stats<<<dim3(KK, BB), 256>>>();
    lamc_part<<<dim3(32, BB), 256>>>();
    lamc_reduce<<<(BB * KK * VV + 255) / 256, 256>>>();
    lambda_main<<<dim3(TT_ / M_TT, BB), 256, main_smem>>>(pw, pb, out);
}

// round 13
// speedup vs baseline: 1.5770x; 1.0089x over previous
#include <cuda_runtime.h>
#include <cuda_bf16.h>
#include <cstdint>
#include <cstddef>

// Problem constants
#define BB   8
#define CC   512
#define TT_  4096
#define HH   4
#define KK   16
#define VV   128
#define RR   15
#define NCH  208          // 64 q + 16 k + 128 v
#define NQ   64
#define NV   128
#define MPAD 256
#define NT   32768        // BB*TT_
#define PSTG 16           // paired stages: 8x (xh: Wh+Wl) + 8x (xl: Wh)

// ---------------- scratch ----------------
__device__ float g_proj[(size_t)BB * NCH * TT_];        // [8][208][4096]
__device__ float g_scale[192];
__device__ float g_shift[192];
__device__ float g_part[(size_t)BB * 32 * KK * VV];
__device__ float g_lambda[(size_t)BB * KK * VV];
__device__ float g_bnp[192 * 8 * 2];
__device__ float g_kstat[BB * KK * 2];                  // per (b,k): max, 1/sumexp
__device__ __nv_bfloat16 g_Wh[MPAD * CC];
__device__ __nv_bfloat16 g_Wl[MPAD * CC];
__device__ __nv_bfloat16 g_xh[(size_t)NT * CC];         // [b*t][c]
__device__ __nv_bfloat16 g_xl[(size_t)NT * CC];

// ---------------- helpers ----------------
__device__ __forceinline__ uint32_t smem_u32(const void* p) {
    uint32_t a;
    asm("{ .reg .u64 t; cvta.to.shared.u64 t, %1; cvt.u32.u64 %0, t; }" : "=r"(a) : "l"(p));
    return a;
}
#define SWZ128(off) ((off) ^ (((off) >> 3) & 0x70))
#define CP_ASYNC16(dst, src) \
    asm volatile("cp.async.cg.shared.global [%0], [%1], 16;" :: "r"(dst), "l"(src))

__device__ __forceinline__ void ldsm_x4(uint32_t& r0, uint32_t& r1, uint32_t& r2, uint32_t& r3,
                                        uint32_t addr) {
    asm volatile("ldmatrix.sync.aligned.m8n8.x4.shared.b16 {%0,%1,%2,%3}, [%4];"
        : "=r"(r0), "=r"(r1), "=r"(r2), "=r"(r3) : "r"(addr));
}
#define MMA16816(c, a, b0, b1) \
    asm volatile("mma.sync.aligned.m16n8k16.row.col.f32.bf16.bf16.f32 " \
        "{%0,%1,%2,%3}, {%4,%5,%6,%7}, {%8,%9}, {%0,%1,%2,%3};" \
        : "+f"((c)[0]), "+f"((c)[1]), "+f"((c)[2]), "+f"((c)[3]) \
        : "r"((a)[0]), "r"((a)[1]), "r"((a)[2]), "r"((a)[3]), "r"(b0), "r"(b1))

// ---------------- pack W, split into bf16 hi/lo (padded to 256 rows) ----------------
__global__ void pack_w_split(const float* __restrict__ Wq, const float* __restrict__ Wk,
                             const float* __restrict__ Wv) {
    int i = blockIdx.x * 256 + threadIdx.x;
    if (i >= MPAD * CC) return;
    int ch = i / CC, c = i % CC;
    float w = 0.f;
    if (ch < 64)       w = Wq[ch * CC + c];
    else if (ch < 80)  w = Wk[(ch - 64) * CC + c];
    else if (ch < NCH) w = Wv[(ch - 80) * CC + c];
    __nv_bfloat16 h = __float2bfloat16(w);
    g_Wh[i] = h;
    g_Wl[i] = __float2bfloat16(w - __bfloat162float(h));
}

// ---------------- transpose + split x: [b][c][t] f32 -> [b*t][c] bf16 hi/lo ----------------
__global__ __launch_bounds__(256) void xsplit(const float* __restrict__ x, int b0) {
    __shared__ float s[64][33];
    const int b = blockIdx.z + b0, c0 = blockIdx.y * 64, t0 = blockIdx.x * 32;
    const int tid = threadIdx.x;
    const int tx = tid & 31, cy = tid >> 5;   // cy 0..7
    const float* xp = x + ((size_t)b * CC + c0) * TT_ + t0;
#pragma unroll
    for (int j = 0; j < 8; j++)
        s[cy + j * 8][tx] = xp[(size_t)(cy + j * 8) * TT_ + tx];
    __syncthreads();
    const size_t row0 = (size_t)b * TT_ + t0;
    const int lane = tid & 31, w = tid >> 5;
    uint32_t* oh = (uint32_t*)g_xh;
    uint32_t* ol = (uint32_t*)g_xl;
#pragma unroll
    for (int j = 0; j < 4; j++) {
        const int r = w * 4 + j;          // t index in tile
        const float v0 = s[lane * 2][r];
        const float v1 = s[lane * 2 + 1][r];
        __nv_bfloat162 h2 = make_bfloat162(__float2bfloat16(v0), __float2bfloat16(v1));
        __nv_bfloat162 l2 = make_bfloat162(__float2bfloat16(v0 - __bfloat162float(h2.x)),
                                           __float2bfloat16(v1 - __bfloat162float(h2.y)));
        const size_t idx = ((row0 + r) * CC + c0) / 2 + lane;
        oh[idx] = *(uint32_t*)&h2;
        ol[idx] = *(uint32_t*)&l2;
    }
}

// ---------------- mma.sync bf16 projection GEMM ----------------
// D[ch][gt] = Wh.xh + Wl.xh + Wh.xl
// CTA 128(m) x 128(n), 128 threads (4 warps, 2M x 2N), warp 64x64.
// Stage = A0 16KB | A1 16KB | B 16KB = 48KB, double-buffered (96KB) -> 2 CTAs/SM.
#define STG_BYTES 49152
#define GM_SMEM (2 * STG_BYTES)

__global__ __launch_bounds__(128, 2) void gemm_mma() {
    extern __shared__ __align__(128) char smem[];
    const uint32_t sb = smem_u32(smem);
    const int tid = threadIdx.x;
    const int wid = tid >> 5, lane = tid & 31;
    const int n0 = blockIdx.x * 128;       // flattened b*t column base
    const int m0 = blockIdx.y * 128;       // channel base
    const int wm = wid & 1, wn = wid >> 1; // warp tile origin (m:2, n:2)
    const int ml = lane >> 3, rin = lane & 7;

    float acc[4][8][4];
#pragma unroll
    for (int i = 0; i < 4; i++)
#pragma unroll
        for (int j = 0; j < 8; j++)
#pragma unroll
            for (int k = 0; k < 4; k++) acc[i][j][k] = 0.f;

    auto issue = [&](int p) {
        const bool dual = p < 8;
        const int koff = (p & 7) * 64;
        const __nv_bfloat16* bseg = dual ? g_xh : g_xl;
        const uint32_t st = sb + (p & 1) * STG_BYTES;
#pragma unroll
        for (int j = 0; j < 8; j++) {
            int idx = tid + j * 128;
            int r = idx >> 3, cc = idx & 7;
            const uint32_t dsw = SWZ128((uint32_t)(r * 128 + cc * 16));
            CP_ASYNC16(st + dsw, g_Wh + (size_t)(m0 + r) * CC + koff + cc * 8);
            if (dual)
                CP_ASYNC16(st + 16384 + dsw, g_Wl + (size_t)(m0 + r) * CC + koff + cc * 8);
            CP_ASYNC16(st + 32768 + dsw, bseg + (size_t)(n0 + r) * CC + koff + cc * 8);
        }
        asm volatile("cp.async.commit_group;");
    };

    auto compute_pair = [&](uint32_t stA0, uint32_t stA1, uint32_t stB, bool dual) {
#pragma unroll
        for (int ks = 0; ks < 4; ks++) {
            uint32_t bfr[4][4];
#pragma unroll
            for (int bi = 0; bi < 4; bi++) {
                const int n = wn * 64 + bi * 16 + (ml >> 1) * 8 + rin;
                const int kc = 2 * ks + (ml & 1);
                ldsm_x4(bfr[bi][0], bfr[bi][1], bfr[bi][2], bfr[bi][3],
                        stB + n * 128 + ((kc ^ (n & 7)) << 4));
            }
            uint32_t a[4][4];
#pragma unroll
            for (int mi = 0; mi < 4; mi++) {
                const int row = wm * 64 + mi * 16 + (ml & 1) * 8 + rin;
                const int kc = 2 * ks + (ml >> 1);
                ldsm_x4(a[mi][0], a[mi][1], a[mi][2], a[mi][3],
                        stA0 + row * 128 + ((kc ^ (row & 7)) << 4));
            }
#pragma unroll
            for (int mi = 0; mi < 4; mi++)
#pragma unroll
                for (int ni = 0; ni < 8; ni++)
                    MMA16816(acc[mi][ni], a[mi],
                             bfr[ni >> 1][(ni & 1) * 2], bfr[ni >> 1][(ni & 1) * 2 + 1]);
            if (dual) {
#pragma unroll
                for (int mi = 0; mi < 4; mi++) {
                    const int row = wm * 64 + mi * 16 + (ml & 1) * 8 + rin;
                    const int kc = 2 * ks + (ml >> 1);
                    ldsm_x4(a[mi][0], a[mi][1], a[mi][2], a[mi][3],
                            stA1 + row * 128 + ((kc ^ (row & 7)) << 4));
                }
#pragma unroll
                for (int mi = 0; mi < 4; mi++)
#pragma unroll
                    for (int ni = 0; ni < 8; ni++)
                        MMA16816(acc[mi][ni], a[mi],
                                 bfr[ni >> 1][(ni & 1) * 2], bfr[ni >> 1][(ni & 1) * 2 + 1]);
            }
        }
    };

    issue(0);
#pragma unroll 1
    for (int p = 0; p < PSTG; p++) {
        if (p + 1 < PSTG) {
            issue(p + 1);
            asm volatile("cp.async.wait_group 1;");
        } else {
            asm volatile("cp.async.wait_group 0;");
        }
        __syncthreads();
        const uint32_t st = sb + (p & 1) * STG_BYTES;
        compute_pair(st, st + 16384, st + 32768, p < 8);
        __syncthreads();
    }

    // epilogue
    const int b = n0 >> 12;
    const int t0 = n0 & (TT_ - 1);
#pragma unroll
    for (int mi = 0; mi < 4; mi++) {
#pragma unroll
        for (int h = 0; h < 2; h++) {
            const int ch = m0 + wm * 64 + mi * 16 + (lane >> 2) + h * 8;
            if (ch < NCH) {
                float* p = g_proj + ((size_t)b * NCH + ch) * TT_ + t0 + wn * 64 + (lane & 3) * 2;
#pragma unroll
                for (int ni = 0; ni < 8; ni++) {
                    float2 v = make_float2(acc[mi][ni][h * 2], acc[mi][ni][h * 2 + 1]);
                    *(float2*)(p + ni * 8) = v;
                }
            }
        }
    }
}

// ---------------- BN stats phase 1: per-(channel, batch) partial sums ----------------
__global__ __launch_bounds__(256) void bn_part() {
    const int ci = blockIdx.x, bb = blockIdx.y;
    const int ch = ci < 64 ? ci : ci + 16;
    const int tid = threadIdx.x;
    const float* p = g_proj + ((size_t)bb * NCH + ch) * TT_;
    float s = 0.f, s2 = 0.f;
    for (int i = tid * 4; i < TT_; i += 256 * 4) {
        float4 v = *(const float4*)(p + i);
        s += v.x + v.y + v.z + v.w;
        s2 += v.x * v.x + v.y * v.y + v.z * v.z + v.w * v.w;
    }
#pragma unroll
    for (int o = 16; o > 0; o >>= 1) {
        s  += __shfl_down_sync(0xffffffffu, s, o);
        s2 += __shfl_down_sync(0xffffffffu, s2, o);
    }
    __shared__ float ws[8], ws2[8];
    if ((tid & 31) == 0) { ws[tid >> 5] = s; ws2[tid >> 5] = s2; }
    __syncthreads();
    if (tid == 0) {
        float t = 0.f, t2 = 0.f;
#pragma unroll
        for (int w = 0; w < 8; w++) { t += ws[w]; t2 += ws2[w]; }
        g_bnp[(ci * 8 + bb) * 2]     = t;
        g_bnp[(ci * 8 + bb) * 2 + 1] = t2;
    }
}

// ---------------- BN stats phase 2: fold to per-channel affine ----------------
__global__ void bn_final(const float* __restrict__ gq, const float* __restrict__ bq,
                         const float* __restrict__ gv, const float* __restrict__ bv) {
    const int ci = threadIdx.x;
    if (ci >= 192) return;
    float s = 0.f, s2 = 0.f;
#pragma unroll
    for (int bb = 0; bb < 8; bb++) {
        s  += g_bnp[(ci * 8 + bb) * 2];
        s2 += g_bnp[(ci * 8 + bb) * 2 + 1];
    }
    const float N = (float)(BB * TT_);
    float mean = s / N;
    float var = s2 / N - mean * mean;
    float g = ci < 64 ? gq[ci] : gv[ci - 64];
    float be = ci < 64 ? bq[ci] : bv[ci - 64];
    float sc = g * rsqrtf(var + 1e-5f);
    g_scale[ci] = sc;
    g_shift[ci] = be - mean * sc;
}

// ---------------- k softmax stats: per (b,k) row max and 1/sumexp ----------------
__global__ __launch_bounds__(256) void k_stats() {
    const int b = blockIdx.y, k = blockIdx.x;
    const float* row = g_proj + ((size_t)b * NCH + 64 + k) * TT_;
    const int tid = threadIdx.x;
    float m = -1e30f;
    for (int i = tid * 4; i < TT_; i += 1024) {
        float4 v = *(const float4*)(row + i);
        m = fmaxf(m, fmaxf(fmaxf(v.x, v.y), fmaxf(v.z, v.w)));
    }
#pragma unroll
    for (int o = 16; o > 0; o >>= 1) m = fmaxf(m, __shfl_xor_sync(0xffffffffu, m, o));
    __shared__ float wm[8];
    if ((tid & 31) == 0) wm[tid >> 5] = m;
    __syncthreads();
    m = fmaxf(fmaxf(fmaxf(wm[0], wm[1]), fmaxf(wm[2], wm[3])),
              fmaxf(fmaxf(wm[4], wm[5]), fmaxf(wm[6], wm[7])));
    float s = 0.f;
    for (int i = tid * 4; i < TT_; i += 1024) {
        float4 v = *(const float4*)(row + i);
        s += expf(v.x - m) + expf(v.y - m) + expf(v.z - m) + expf(v.w - m);
    }
#pragma unroll
    for (int o = 16; o > 0; o >>= 1) s += __shfl_xor_sync(0xffffffffu, s, o);
    __shared__ float wsum[8];
    if ((tid & 31) == 0) wsum[tid >> 5] = s;
    __syncthreads();
    if (tid == 0) {
        float t = 0.f;
#pragma unroll
        for (int w = 0; w < 8; w++) t += wsum[w];
        g_kstat[(b * KK + k) * 2]     = m;
        g_kstat[(b * KK + k) * 2 + 1] = 1.f / t;
    }
}

// ---------------- lambda_c partials (softmax applied inline) ----------------
__global__ __launch_bounds__(256) void lamc_part() {
    const int b = blockIdx.y, chunk = blockIdx.x;
    const int t0 = chunk * 128;
    const float* pk = g_proj + ((size_t)b * NCH + 64) * TT_ + t0;
    const float* pv = g_proj + ((size_t)b * NCH + 80) * TT_ + t0;
    __shared__ float sk[KK][33];
    __shared__ float svt[32][132];
    __shared__ float skm[KK], ski[KK];
    const int tid = threadIdx.x;
    const int k = tid & 15, vg = tid >> 4;
    if (tid < KK) {
        skm[tid] = g_kstat[(b * KK + tid) * 2];
        ski[tid] = g_kstat[(b * KK + tid) * 2 + 1];
    }
    __syncthreads();
    float acc[8];
#pragma unroll
    for (int j = 0; j < 8; j++) acc[j] = 0.f;

#pragma unroll 1
    for (int sub = 0; sub < 4; sub++) {
        for (int i = tid; i < KK * 32; i += 256) {
            int kk = i >> 5, tt = i & 31;
            float raw = pk[(size_t)kk * TT_ + sub * 32 + tt];
            sk[kk][tt] = expf(raw - skm[kk]) * ski[kk];
        }
        for (int i = tid; i < NV * 32; i += 256) {
            int v = i >> 5, tt = i & 31;
            svt[tt][v] = pv[(size_t)v * TT_ + sub * 32 + tt];
        }
        __syncthreads();
#pragma unroll
        for (int t = 0; t < 32; t++) {
            const float a = sk[k][t];
            const float4 v0 = *(const float4*)&svt[t][vg * 8];
            const float4 v1 = *(const float4*)&svt[t][vg * 8 + 4];
            acc[0] += a * v0.x; acc[1] += a * v0.y; acc[2] += a * v0.z; acc[3] += a * v0.w;
            acc[4] += a * v1.x; acc[5] += a * v1.y; acc[6] += a * v1.z; acc[7] += a * v1.w;
        }
        __syncthreads();
    }
    float* pp = g_part + (((size_t)b * 32 + chunk) * KK + k) * VV + vg * 8;
#pragma unroll
    for (int j = 0; j < 8; j++) pp[j] = acc[j];
}

// ---------------- reduce partials + fold v BN affine ----------------
__global__ void lamc_reduce() {
    const int i = blockIdx.x * 256 + threadIdx.x;
    if (i >= BB * KK * VV) return;
    const int v = i & 127;
    const int b = i >> 11;
    const float* p = g_part + (size_t)b * 32 * KK * VV + (i & 2047);
    float s = 0.f;
#pragma unroll 1
    for (int c = 0; c < 32; c++) s += p[(size_t)c * KK * VV];
    g_lambda[i] = g_scale[64 + v] * s + g_shift[64 + v];
}

// ---------------- fused output ----------------
#define M_TT 128
#define M_HW 144

__global__ __launch_bounds__(256) void lambda_main(const float* __restrict__ pos_w,
                                                   const float* __restrict__ pos_b,
                                                   float* __restrict__ out) {
    extern __shared__ float sm[];
    float* sq  = sm;
    float* sv  = sm + NQ * M_TT;
    float* slc = sv + NV * M_HW;
    float* spw = slc + KK * VV;
    float* spb = spw + KK * RR;

    const int b = blockIdx.y;
    const int t0 = blockIdx.x * M_TT;
    const int tid = threadIdx.x;
    const float* pq = g_proj + (size_t)b * NCH * TT_;
    const float* pv = pq + (size_t)80 * TT_;

    for (int i = tid; i < NQ * M_TT; i += 256) {
        int ch = i >> 7, t = i & 127;
        sq[i] = pq[(size_t)ch * TT_ + t0 + t] * g_scale[ch] + g_shift[ch];
    }
    for (int i = tid; i < NV * M_HW; i += 256) {
        int v = i / M_HW, tr = i % M_HW;
        float val = 0.f;
        if (tr < M_TT + RR - 1) {
            int tg = t0 - (RR / 2) + tr;
            if (tg >= 0 && tg < TT_)
                val = pv[(size_t)v * TT_ + tg] * g_scale[64 + v] + g_shift[64 + v];
        }
        sv[i] = val;
    }
    for (int i = tid; i < KK * VV; i += 256) slc[i] = g_lambda[(size_t)b * KK * VV + i];
    if (tid < KK * RR) spw[tid] = pos_w[tid];
    if (tid < KK) spb[tid] = pos_b[tid];
    __syncthreads();

    const int t = tid & 127;
    const int vh = tid >> 7;

    float q[NQ];
#pragma unroll
    for (int ch = 0; ch < NQ; ch++) q[ch] = sq[ch * M_TT + t];

    float qw[HH][RR];
    float qb[HH] = {0.f, 0.f, 0.f, 0.f};
#pragma unroll
    for (int h = 0; h < HH; h++)
#pragma unroll
        for (int r = 0; r < RR; r++) qw[h][r] = 0.f;

#pragma unroll
    for (int k = 0; k < KK; k++) {
        const float pb = spb[k];
#pragma unroll
        for (int h = 0; h < HH; h++) qb[h] += q[h * KK + k] * pb;
#pragma unroll
        for (int r = 0; r < RR; r++) {
            const float w = spw[k * RR + r];
#pragma unroll
            for (int h = 0; h < HH; h++) qw[h][r] += q[h * KK + k] * w;
        }
    }

    float* ob = out + (size_t)b * 512 * TT_ + t0 + t;
#pragma unroll 2
    for (int v = 0; v < 64; v++) {
        const int vv = vh * 64 + v;
        float a0 = qb[0], a1 = qb[1], a2 = qb[2], a3 = qb[3];
#pragma unroll
        for (int k = 0; k < KK; k++) {
            const float l = slc[k * VV + vv];
            a0 += q[k] * l;
            a1 += q[KK + k] * l;
            a2 += q[2 * KK + k] * l;
            a3 += q[3 * KK + k] * l;
        }
        const float* vp = sv + vv * M_HW + t;
#pragma unroll
        for (int r = 0; r < RR; r++) {
            const float x = vp[r];
            a0 += qw[0][r] * x;
            a1 += qw[1][r] * x;
            a2 += qw[2][r] * x;
            a3 += qw[3][r] * x;
        }
        ob[(size_t)(0 * VV + vv) * TT_] = a0;
        ob[(size_t)(1 * VV + vv) * TT_] = a1;
        ob[(size_t)(2 * VV + vv) * TT_] = a2;
        ob[(size_t)(3 * VV + vv) * TT_] = a3;
    }
}

// ---------------- launch ----------------
extern "C" void kernel_launch(void* const* d_in, const int* in_sizes, int n_in,
                              void* d_out, int out_size) {
    const float* x  = (const float*)d_in[0];
    const float* Wq = (const float*)d_in[1];
    const float* Wk = (const float*)d_in[2];
    const float* Wv = (const float*)d_in[3];
    const float* gq = (const float*)d_in[4];
    const float* bq = (const float*)d_in[5];
    const float* gv = (const float*)d_in[6];
    const float* bv = (const float*)d_in[7];
    const float* pw = (const float*)d_in[8];
    const float* pb = (const float*)d_in[9];
    float* out = (float*)d_out;

    const size_t main_smem = (size_t)(NQ * M_TT + NV * M_HW + KK * VV + KK * RR + KK) * sizeof(float);
    cudaFuncSetAttribute(lambda_main, cudaFuncAttributeMaxDynamicSharedMemorySize, (int)main_smem);
    cudaFuncSetAttribute(gemm_mma, cudaFuncAttributeMaxDynamicSharedMemorySize, GM_SMEM);

    // gemm_mma is deliberately the 4th launch (ncu capture slot)
    xsplit<<<dim3(TT_ / 32, CC / 64, 4), 256>>>(x, 0);
    xsplit<<<dim3(TT_ / 32, CC / 64, 4), 256>>>(x, 4);
    pack_w_split<<<(MPAD * CC + 255) / 256, 256>>>(Wq, Wk, Wv);
    gemm_mma<<<dim3(NT / 128, 2), 128, GM_SMEM>>>();
    bn_part<<<dim3(192, 8), 256>>>();
    bn_final<<<1, 192>>>(gq, bq, gv, bv);
    k_stats<<<dim3(KK, BB), 256>>>();
    lamc_part<<<dim3(32, BB), 256>>>();
    lamc_reduce<<<(BB * KK * VV + 255) / 256, 256>>>();
    lambda_main<<<dim3(TT_ / M_TT, BB), 256, main_smem>>>(pw, pb, out);
}

// round 14
// speedup vs baseline: 1.5777x; 1.0004x over previous
#include <cuda_runtime.h>
#include <cuda_bf16.h>
#include <cstdint>
#include <cstddef>

// Problem constants
#define BB   8
#define CC   512
#define TT_  4096
#define HH   4
#define KK   16
#define VV   128
#define RR   15
#define NCH  208          // 64 q + 16 k + 128 v
#define NQ   64
#define NV   128
#define MPAD 256
#define NT   32768        // BB*TT_
#define PSTG 16           // paired stages: 8x (xh: Wh+Wl) + 8x (xl: Wh)

// ---------------- scratch ----------------
__device__ float g_proj[(size_t)BB * NCH * TT_];        // [8][208][4096]
__device__ float g_scale[192];
__device__ float g_shift[192];
__device__ float g_part[(size_t)BB * 32 * KK * VV];
__device__ float g_lambda[(size_t)BB * KK * VV];
__device__ float g_bnp[192 * 8 * 2];
__device__ float g_kstat[BB * KK * 2];                  // per (b,k): max, 1/sumexp
__device__ __nv_bfloat16 g_Wh[MPAD * CC];
__device__ __nv_bfloat16 g_Wl[MPAD * CC];
__device__ __nv_bfloat16 g_xh[(size_t)NT * CC];         // [b*t][c]
__device__ __nv_bfloat16 g_xl[(size_t)NT * CC];

// ---------------- helpers ----------------
__device__ __forceinline__ uint32_t smem_u32(const void* p) {
    uint32_t a;
    asm("{ .reg .u64 t; cvta.to.shared.u64 t, %1; cvt.u32.u64 %0, t; }" : "=r"(a) : "l"(p));
    return a;
}
#define SWZ128(off) ((off) ^ (((off) >> 3) & 0x70))
#define CP_ASYNC16(dst, src) \
    asm volatile("cp.async.cg.shared.global [%0], [%1], 16;" :: "r"(dst), "l"(src))

__device__ __forceinline__ void ldsm_x4(uint32_t& r0, uint32_t& r1, uint32_t& r2, uint32_t& r3,
                                        uint32_t addr) {
    asm volatile("ldmatrix.sync.aligned.m8n8.x4.shared.b16 {%0,%1,%2,%3}, [%4];"
        : "=r"(r0), "=r"(r1), "=r"(r2), "=r"(r3) : "r"(addr));
}
#define MMA16816(c, a, b0, b1) \
    asm volatile("mma.sync.aligned.m16n8k16.row.col.f32.bf16.bf16.f32 " \
        "{%0,%1,%2,%3}, {%4,%5,%6,%7}, {%8,%9}, {%0,%1,%2,%3};" \
        : "+f"((c)[0]), "+f"((c)[1]), "+f"((c)[2]), "+f"((c)[3]) \
        : "r"((a)[0]), "r"((a)[1]), "r"((a)[2]), "r"((a)[3]), "r"(b0), "r"(b1))

// ---------------- pack W, split into bf16 hi/lo (padded to 256 rows) ----------------
__global__ void pack_w_split(const float* __restrict__ Wq, const float* __restrict__ Wk,
                             const float* __restrict__ Wv) {
    int i = blockIdx.x * 256 + threadIdx.x;
    if (i >= MPAD * CC) return;
    int ch = i / CC, c = i % CC;
    float w = 0.f;
    if (ch < 64)       w = Wq[ch * CC + c];
    else if (ch < 80)  w = Wk[(ch - 64) * CC + c];
    else if (ch < NCH) w = Wv[(ch - 80) * CC + c];
    __nv_bfloat16 h = __float2bfloat16(w);
    g_Wh[i] = h;
    g_Wl[i] = __float2bfloat16(w - __bfloat162float(h));
}

// ---------------- transpose + split x: [b][c][t] f32 -> [b*t][c] bf16 hi/lo ----------------
__global__ __launch_bounds__(256) void xsplit(const float* __restrict__ x, int b0) {
    __shared__ float s[64][33];
    const int b = blockIdx.z + b0, c0 = blockIdx.y * 64, t0 = blockIdx.x * 32;
    const int tid = threadIdx.x;
    const int tx = tid & 31, cy = tid >> 5;   // cy 0..7
    const float* xp = x + ((size_t)b * CC + c0) * TT_ + t0;
#pragma unroll
    for (int j = 0; j < 8; j++)
        s[cy + j * 8][tx] = xp[(size_t)(cy + j * 8) * TT_ + tx];
    __syncthreads();
    const size_t row0 = (size_t)b * TT_ + t0;
    const int lane = tid & 31, w = tid >> 5;
    uint32_t* oh = (uint32_t*)g_xh;
    uint32_t* ol = (uint32_t*)g_xl;
#pragma unroll
    for (int j = 0; j < 4; j++) {
        const int r = w * 4 + j;          // t index in tile
        const float v0 = s[lane * 2][r];
        const float v1 = s[lane * 2 + 1][r];
        __nv_bfloat162 h2 = make_bfloat162(__float2bfloat16(v0), __float2bfloat16(v1));
        __nv_bfloat162 l2 = make_bfloat162(__float2bfloat16(v0 - __bfloat162float(h2.x)),
                                           __float2bfloat16(v1 - __bfloat162float(h2.y)));
        const size_t idx = ((row0 + r) * CC + c0) / 2 + lane;
        oh[idx] = *(uint32_t*)&h2;
        ol[idx] = *(uint32_t*)&l2;
    }
}

// ---------------- mma.sync bf16 projection GEMM ----------------
// D[ch][gt] = Wh.xh + Wl.xh + Wh.xl
// CTA 128(m) x 128(n), 128 threads (4 warps, 2M x 2N), warp 64x64.
// Stage = A0 16KB | A1 16KB | B 16KB = 48KB, double-buffered (96KB) -> 2 CTAs/SM.
#define STG_BYTES 49152
#define GM_SMEM (2 * STG_BYTES)

__global__ __launch_bounds__(128, 2) void gemm_mma() {
    extern __shared__ __align__(128) char smem[];
    const uint32_t sb = smem_u32(smem);
    const int tid = threadIdx.x;
    const int wid = tid >> 5, lane = tid & 31;
    const int n0 = blockIdx.x * 128;       // flattened b*t column base
    const int m0 = blockIdx.y * 128;       // channel base
    const int wm = wid & 1, wn = wid >> 1; // warp tile origin (m:2, n:2)
    const int ml = lane >> 3, rin = lane & 7;

    float acc[4][8][4];
#pragma unroll
    for (int i = 0; i < 4; i++)
#pragma unroll
        for (int j = 0; j < 8; j++)
#pragma unroll
            for (int k = 0; k < 4; k++) acc[i][j][k] = 0.f;

    auto issue = [&](int p) {
        const bool dual = p < 8;
        const int koff = (p & 7) * 64;
        const __nv_bfloat16* bseg = dual ? g_xh : g_xl;
        const uint32_t st = sb + (p & 1) * STG_BYTES;
#pragma unroll
        for (int j = 0; j < 8; j++) {
            int idx = tid + j * 128;
            int r = idx >> 3, cc = idx & 7;
            const uint32_t dsw = SWZ128((uint32_t)(r * 128 + cc * 16));
            CP_ASYNC16(st + dsw, g_Wh + (size_t)(m0 + r) * CC + koff + cc * 8);
            if (dual)
                CP_ASYNC16(st + 16384 + dsw, g_Wl + (size_t)(m0 + r) * CC + koff + cc * 8);
            CP_ASYNC16(st + 32768 + dsw, bseg + (size_t)(n0 + r) * CC + koff + cc * 8);
        }
        asm volatile("cp.async.commit_group;");
    };

    auto compute_pair = [&](uint32_t stA0, uint32_t stA1, uint32_t stB, bool dual) {
#pragma unroll
        for (int ks = 0; ks < 4; ks++) {
            uint32_t bfr[4][4];
#pragma unroll
            for (int bi = 0; bi < 4; bi++) {
                const int n = wn * 64 + bi * 16 + (ml >> 1) * 8 + rin;
                const int kc = 2 * ks + (ml & 1);
                ldsm_x4(bfr[bi][0], bfr[bi][1], bfr[bi][2], bfr[bi][3],
                        stB + n * 128 + ((kc ^ (n & 7)) << 4));
            }
            uint32_t a[4][4];
#pragma unroll
            for (int mi = 0; mi < 4; mi++) {
                const int row = wm * 64 + mi * 16 + (ml & 1) * 8 + rin;
                const int kc = 2 * ks + (ml >> 1);
                ldsm_x4(a[mi][0], a[mi][1], a[mi][2], a[mi][3],
                        stA0 + row * 128 + ((kc ^ (row & 7)) << 4));
            }
#pragma unroll
            for (int mi = 0; mi < 4; mi++)
#pragma unroll
                for (int ni = 0; ni < 8; ni++)
                    MMA16816(acc[mi][ni], a[mi],
                             bfr[ni >> 1][(ni & 1) * 2], bfr[ni >> 1][(ni & 1) * 2 + 1]);
            if (dual) {
#pragma unroll
                for (int mi = 0; mi < 4; mi++) {
                    const int row = wm * 64 + mi * 16 + (ml & 1) * 8 + rin;
                    const int kc = 2 * ks + (ml >> 1);
                    ldsm_x4(a[mi][0], a[mi][1], a[mi][2], a[mi][3],
                            stA1 + row * 128 + ((kc ^ (row & 7)) << 4));
                }
#pragma unroll
                for (int mi = 0; mi < 4; mi++)
#pragma unroll
                    for (int ni = 0; ni < 8; ni++)
                        MMA16816(acc[mi][ni], a[mi],
                                 bfr[ni >> 1][(ni & 1) * 2], bfr[ni >> 1][(ni & 1) * 2 + 1]);
            }
        }
    };

    issue(0);
#pragma unroll 1
    for (int p = 0; p < PSTG; p++) {
        if (p + 1 < PSTG) {
            issue(p + 1);
            asm volatile("cp.async.wait_group 1;");
        } else {
            asm volatile("cp.async.wait_group 0;");
        }
        __syncthreads();
        const uint32_t st = sb + (p & 1) * STG_BYTES;
        compute_pair(st, st + 16384, st + 32768, p < 8);
        __syncthreads();
    }

    // epilogue
    const int b = n0 >> 12;
    const int t0 = n0 & (TT_ - 1);
#pragma unroll
    for (int mi = 0; mi < 4; mi++) {
#pragma unroll
        for (int h = 0; h < 2; h++) {
            const int ch = m0 + wm * 64 + mi * 16 + (lane >> 2) + h * 8;
            if (ch < NCH) {
                float* p = g_proj + ((size_t)b * NCH + ch) * TT_ + t0 + wn * 64 + (lane & 3) * 2;
#pragma unroll
                for (int ni = 0; ni < 8; ni++) {
                    float2 v = make_float2(acc[mi][ni][h * 2], acc[mi][ni][h * 2 + 1]);
                    *(float2*)(p + ni * 8) = v;
                }
            }
        }
    }
}

// ---------------- merged stats: BN partials (ci<192) + k softmax stats (ci>=192) ----------------
__global__ __launch_bounds__(256) void stats_part() {
    const int ci = blockIdx.x, bb = blockIdx.y;
    const int tid = threadIdx.x;
    if (ci < 192) {
        const int ch = ci < 64 ? ci : ci + 16;
        const float* p = g_proj + ((size_t)bb * NCH + ch) * TT_;
        float s = 0.f, s2 = 0.f;
        for (int i = tid * 4; i < TT_; i += 256 * 4) {
            float4 v = *(const float4*)(p + i);
            s += v.x + v.y + v.z + v.w;
            s2 += v.x * v.x + v.y * v.y + v.z * v.z + v.w * v.w;
        }
#pragma unroll
        for (int o = 16; o > 0; o >>= 1) {
            s  += __shfl_down_sync(0xffffffffu, s, o);
            s2 += __shfl_down_sync(0xffffffffu, s2, o);
        }
        __shared__ float ws[8], ws2[8];
        if ((tid & 31) == 0) { ws[tid >> 5] = s; ws2[tid >> 5] = s2; }
        __syncthreads();
        if (tid == 0) {
            float t = 0.f, t2 = 0.f;
#pragma unroll
            for (int w = 0; w < 8; w++) { t += ws[w]; t2 += ws2[w]; }
            g_bnp[(ci * 8 + bb) * 2]     = t;
            g_bnp[(ci * 8 + bb) * 2 + 1] = t2;
        }
    } else {
        const int k = ci - 192;
        const float* row = g_proj + ((size_t)bb * NCH + 64 + k) * TT_;
        float m = -1e30f;
        for (int i = tid * 4; i < TT_; i += 1024) {
            float4 v = *(const float4*)(row + i);
            m = fmaxf(m, fmaxf(fmaxf(v.x, v.y), fmaxf(v.z, v.w)));
        }
#pragma unroll
        for (int o = 16; o > 0; o >>= 1) m = fmaxf(m, __shfl_xor_sync(0xffffffffu, m, o));
        __shared__ float wm[8];
        if ((tid & 31) == 0) wm[tid >> 5] = m;
        __syncthreads();
        m = fmaxf(fmaxf(fmaxf(wm[0], wm[1]), fmaxf(wm[2], wm[3])),
                  fmaxf(fmaxf(wm[4], wm[5]), fmaxf(wm[6], wm[7])));
        float s = 0.f;
        for (int i = tid * 4; i < TT_; i += 1024) {
            float4 v = *(const float4*)(row + i);
            s += expf(v.x - m) + expf(v.y - m) + expf(v.z - m) + expf(v.w - m);
        }
#pragma unroll
        for (int o = 16; o > 0; o >>= 1) s += __shfl_xor_sync(0xffffffffu, s, o);
        __shared__ float wsum[8];
        if ((tid & 31) == 0) wsum[tid >> 5] = s;
        __syncthreads();
        if (tid == 0) {
            float t = 0.f;
#pragma unroll
            for (int w = 0; w < 8; w++) t += wsum[w];
            g_kstat[(bb * KK + k) * 2]     = m;
            g_kstat[(bb * KK + k) * 2 + 1] = 1.f / t;
        }
    }
}

// ---------------- BN stats phase 2: fold to per-channel affine ----------------
__global__ void bn_final(const float* __restrict__ gq, const float* __restrict__ bq,
                         const float* __restrict__ gv, const float* __restrict__ bv) {
    const int ci = threadIdx.x;
    if (ci >= 192) return;
    float s = 0.f, s2 = 0.f;
#pragma unroll
    for (int bb = 0; bb < 8; bb++) {
        s  += g_bnp[(ci * 8 + bb) * 2];
        s2 += g_bnp[(ci * 8 + bb) * 2 + 1];
    }
    const float N = (float)(BB * TT_);
    float mean = s / N;
    float var = s2 / N - mean * mean;
    float g = ci < 64 ? gq[ci] : gv[ci - 64];
    float be = ci < 64 ? bq[ci] : bv[ci - 64];
    float sc = g * rsqrtf(var + 1e-5f);
    g_scale[ci] = sc;
    g_shift[ci] = be - mean * sc;
}

// ---------------- lambda_c partials (softmax applied inline) ----------------
__global__ __launch_bounds__(256) void lamc_part() {
    const int b = blockIdx.y, chunk = blockIdx.x;
    const int t0 = chunk * 128;
    const float* pk = g_proj + ((size_t)b * NCH + 64) * TT_ + t0;
    const float* pv = g_proj + ((size_t)b * NCH + 80) * TT_ + t0;
    __shared__ float sk[KK][33];
    __shared__ float svt[32][132];
    __shared__ float skm[KK], ski[KK];
    const int tid = threadIdx.x;
    const int k = tid & 15, vg = tid >> 4;
    if (tid < KK) {
        skm[tid] = g_kstat[(b * KK + tid) * 2];
        ski[tid] = g_kstat[(b * KK + tid) * 2 + 1];
    }
    __syncthreads();
    float acc[8];
#pragma unroll
    for (int j = 0; j < 8; j++) acc[j] = 0.f;

#pragma unroll 1
    for (int sub = 0; sub < 4; sub++) {
        for (int i = tid; i < KK * 32; i += 256) {
            int kk = i >> 5, tt = i & 31;
            float raw = pk[(size_t)kk * TT_ + sub * 32 + tt];
            sk[kk][tt] = expf(raw - skm[kk]) * ski[kk];
        }
        for (int i = tid; i < NV * 32; i += 256) {
            int v = i >> 5, tt = i & 31;
            svt[tt][v] = pv[(size_t)v * TT_ + sub * 32 + tt];
        }
        __syncthreads();
#pragma unroll
        for (int t = 0; t < 32; t++) {
            const float a = sk[k][t];
            const float4 v0 = *(const float4*)&svt[t][vg * 8];
            const float4 v1 = *(const float4*)&svt[t][vg * 8 + 4];
            acc[0] += a * v0.x; acc[1] += a * v0.y; acc[2] += a * v0.z; acc[3] += a * v0.w;
            acc[4] += a * v1.x; acc[5] += a * v1.y; acc[6] += a * v1.z; acc[7] += a * v1.w;
        }
        __syncthreads();
    }
    float* pp = g_part + (((size_t)b * 32 + chunk) * KK + k) * VV + vg * 8;
#pragma unroll
    for (int j = 0; j < 8; j++) pp[j] = acc[j];
}

// ---------------- reduce partials + fold v BN affine ----------------
__global__ void lamc_reduce() {
    const int i = blockIdx.x * 256 + threadIdx.x;
    if (i >= BB * KK * VV) return;
    const int v = i & 127;
    const int b = i >> 11;
    const float* p = g_part + (size_t)b * 32 * KK * VV + (i & 2047);
    float s = 0.f;
#pragma unroll 1
    for (int c = 0; c < 32; c++) s += p[(size_t)c * KK * VV];
    g_lambda[i] = g_scale[64 + v] * s + g_shift[64 + v];
}

// ---------------- fused output ----------------
#define M_TT 128
#define M_HW 144

__global__ __launch_bounds__(256) void lambda_main(const float* __restrict__ pos_w,
                                                   const float* __restrict__ pos_b,
                                                   float* __restrict__ out) {
    extern __shared__ float sm[];
    float* sq  = sm;
    float* sv  = sm + NQ * M_TT;
    float* slc = sv + NV * M_HW;
    float* spw = slc + KK * VV;
    float* spb = spw + KK * RR;

    const int b = blockIdx.y;
    const int t0 = blockIdx.x * M_TT;
    const int tid = threadIdx.x;
    const float* pq = g_proj + (size_t)b * NCH * TT_;
    const float* pv = pq + (size_t)80 * TT_;

    for (int i = tid; i < NQ * M_TT; i += 256) {
        int ch = i >> 7, t = i & 127;
        sq[i] = pq[(size_t)ch * TT_ + t0 + t] * g_scale[ch] + g_shift[ch];
    }
    for (int i = tid; i < NV * M_HW; i += 256) {
        int v = i / M_HW, tr = i % M_HW;
        float val = 0.f;
        if (tr < M_TT + RR - 1) {
            int tg = t0 - (RR / 2) + tr;
            if (tg >= 0 && tg < TT_)
                val = pv[(size_t)v * TT_ + tg] * g_scale[64 + v] + g_shift[64 + v];
        }
        sv[i] = val;
    }
    for (int i = tid; i < KK * VV; i += 256) slc[i] = g_lambda[(size_t)b * KK * VV + i];
    if (tid < KK * RR) spw[tid] = pos_w[tid];
    if (tid < KK) spb[tid] = pos_b[tid];
    __syncthreads();

    const int t = tid & 127;
    const int vh = tid >> 7;

    float q[NQ];
#pragma unroll
    for (int ch = 0; ch < NQ; ch++) q[ch] = sq[ch * M_TT + t];

    float qw[HH][RR];
    float qb[HH] = {0.f, 0.f, 0.f, 0.f};
#pragma unroll
    for (int h = 0; h < HH; h++)
#pragma unroll
        for (int r = 0; r < RR; r++) qw[h][r] = 0.f;

#pragma unroll
    for (int k = 0; k < KK; k++) {
        const float pb = spb[k];
#pragma unroll
        for (int h = 0; h < HH; h++) qb[h] += q[h * KK + k] * pb;
#pragma unroll
        for (int r = 0; r < RR; r++) {
            const float w = spw[k * RR + r];
#pragma unroll
            for (int h = 0; h < HH; h++) qw[h][r] += q[h * KK + k] * w;
        }
    }

    float* ob = out + (size_t)b * 512 * TT_ + t0 + t;
#pragma unroll 2
    for (int v = 0; v < 64; v++) {
        const int vv = vh * 64 + v;
        float a0 = qb[0], a1 = qb[1], a2 = qb[2], a3 = qb[3];
#pragma unroll
        for (int k = 0; k < KK; k++) {
            const float l = slc[k * VV + vv];
            a0 += q[k] * l;
            a1 += q[KK + k] * l;
            a2 += q[2 * KK + k] * l;
            a3 += q[3 * KK + k] * l;
        }
        const float* vp = sv + vv * M_HW + t;
#pragma unroll
        for (int r = 0; r < RR; r++) {
            const float x = vp[r];
            a0 += qw[0][r] * x;
            a1 += qw[1][r] * x;
            a2 += qw[2][r] * x;
            a3 += qw[3][r] * x;
        }
        ob[(size_t)(0 * VV + vv) * TT_] = a0;
        ob[(size_t)(1 * VV + vv) * TT_] = a1;
        ob[(size_t)(2 * VV + vv) * TT_] = a2;
        ob[(size_t)(3 * VV + vv) * TT_] = a3;
    }
}

// ---------------- launch ----------------
extern "C" void kernel_launch(void* const* d_in, const int* in_sizes, int n_in,
                              void* d_out, int out_size) {
    const float* x  = (const float*)d_in[0];
    const float* Wq = (const float*)d_in[1];
    const float* Wk = (const float*)d_in[2];
    const float* Wv = (const float*)d_in[3];
    const float* gq = (const float*)d_in[4];
    const float* bq = (const float*)d_in[5];
    const float* gv = (const float*)d_in[6];
    const float* bv = (const float*)d_in[7];
    const float* pw = (const float*)d_in[8];
    const float* pb = (const float*)d_in[9];
    float* out = (float*)d_out;

    const size_t main_smem = (size_t)(NQ * M_TT + NV * M_HW + KK * VV + KK * RR + KK) * sizeof(float);
    cudaFuncSetAttribute(lambda_main, cudaFuncAttributeMaxDynamicSharedMemorySize, (int)main_smem);
    cudaFuncSetAttribute(gemm_mma, cudaFuncAttributeMaxDynamicSharedMemorySize, GM_SMEM);

    // xsplit quarter is deliberately the 4th launch (ncu capture slot this round)
    xsplit<<<dim3(TT_ / 32, CC / 64, 2), 256>>>(x, 0);
    xsplit<<<dim3(TT_ / 32, CC / 64, 2), 256>>>(x, 2);
    xsplit<<<dim3(TT_ / 32, CC / 64, 2), 256>>>(x, 4);
    xsplit<<<dim3(TT_ / 32, CC / 64, 2), 256>>>(x, 6);
    pack_w_split<<<(MPAD * CC + 255) / 256, 256>>>(Wq, Wk, Wv);
    gemm_mma<<<dim3(NT / 128, 2), 128, GM_SMEM>>>();
    stats_part<<<dim3(208, 8), 256>>>();
    bn_final<<<1, 192>>>(gq, bq, gv, bv);
    lamc_part<<<dim3(32, BB), 256>>>();
    lamc_reduce<<<(BB * KK * VV + 255) / 256, 256>>>();
    lambda_main<<<dim3(TT_ / M_TT, BB), 256, main_smem>>>(pw, pb, out);
}

// round 15
// speedup vs baseline: 1.5921x; 1.0091x over previous
#include <cuda_runtime.h>
#include <cuda_bf16.h>
#include <cstdint>
#include <cstddef>

// Problem constants
#define BB   8
#define CC   512
#define TT_  4096
#define HH   4
#define KK   16
#define VV   128
#define RR   15
#define NCH  208          // 64 q + 16 k + 128 v
#define NQ   64
#define NV   128
#define MPAD 256
#define NT   32768        // BB*TT_
#define PSTG 16           // paired stages: 8x (xh: Wh+Wl) + 8x (xl: Wh)

// ---------------- scratch ----------------
__device__ float g_proj[(size_t)BB * NCH * TT_];        // [8][208][4096]
__device__ float g_scale[192];
__device__ float g_shift[192];
__device__ float g_part[(size_t)BB * 32 * KK * VV];
__device__ float g_lambda[(size_t)BB * KK * VV];
__device__ float g_bnp[192 * 8 * 2];
__device__ float g_kstat[BB * KK * 2];                  // per (b,k): max, 1/sumexp
__device__ __nv_bfloat16 g_Wh[MPAD * CC];
__device__ __nv_bfloat16 g_Wl[MPAD * CC];
__device__ __nv_bfloat16 g_xh[(size_t)NT * CC];         // [b*t][c]
__device__ __nv_bfloat16 g_xl[(size_t)NT * CC];

// ---------------- helpers ----------------
__device__ __forceinline__ uint32_t smem_u32(const void* p) {
    uint32_t a;
    asm("{ .reg .u64 t; cvta.to.shared.u64 t, %1; cvt.u32.u64 %0, t; }" : "=r"(a) : "l"(p));
    return a;
}
#define SWZ128(off) ((off) ^ (((off) >> 3) & 0x70))
#define CP_ASYNC16(dst, src) \
    asm volatile("cp.async.cg.shared.global [%0], [%1], 16;" :: "r"(dst), "l"(src))

__device__ __forceinline__ void ldsm_x4(uint32_t& r0, uint32_t& r1, uint32_t& r2, uint32_t& r3,
                                        uint32_t addr) {
    asm volatile("ldmatrix.sync.aligned.m8n8.x4.shared.b16 {%0,%1,%2,%3}, [%4];"
        : "=r"(r0), "=r"(r1), "=r"(r2), "=r"(r3) : "r"(addr));
}
#define MMA16816(c, a, b0, b1) \
    asm volatile("mma.sync.aligned.m16n8k16.row.col.f32.bf16.bf16.f32 " \
        "{%0,%1,%2,%3}, {%4,%5,%6,%7}, {%8,%9}, {%0,%1,%2,%3};" \
        : "+f"((c)[0]), "+f"((c)[1]), "+f"((c)[2]), "+f"((c)[3]) \
        : "r"((a)[0]), "r"((a)[1]), "r"((a)[2]), "r"((a)[3]), "r"(b0), "r"(b1))

// ---------------- pack W, split into bf16 hi/lo (padded to 256 rows) ----------------
__global__ void pack_w_split(const float* __restrict__ Wq, const float* __restrict__ Wk,
                             const float* __restrict__ Wv) {
    int i = blockIdx.x * 256 + threadIdx.x;
    if (i >= MPAD * CC) return;
    int ch = i / CC, c = i % CC;
    float w = 0.f;
    if (ch < 64)       w = Wq[ch * CC + c];
    else if (ch < 80)  w = Wk[(ch - 64) * CC + c];
    else if (ch < NCH) w = Wv[(ch - 80) * CC + c];
    __nv_bfloat16 h = __float2bfloat16(w);
    g_Wh[i] = h;
    g_Wl[i] = __float2bfloat16(w - __bfloat162float(h));
}

// ---------------- transpose + split x v3: [b][c][t] f32 -> [b*t][c] bf16 hi/lo ----------------
// tile 64(t) x 64(c), 256 threads, 16 elems/thread; wide LDG.128/LDS.128/STG.128.
__global__ __launch_bounds__(256) void xsplit(const float* __restrict__ x) {
    __shared__ float s[64][68];               // [t][c], stride 68 floats (16B-aligned rows)
    const int b = blockIdx.z, c0 = blockIdx.y * 64, t0 = blockIdx.x * 64;
    const int tid = threadIdx.x;
    const float* xp = x + ((size_t)b * CC + c0) * TT_ + t0;

    // load: 64 c-rows x 64 t floats; thread: 4x float4 along t, scatter-store transposed
#pragma unroll
    for (int i = 0; i < 4; i++) {
        const int idx = tid + i * 256;
        const int r = idx >> 4, q = idx & 15;             // r = c-row, q = t-quad
        const float4 v = *(const float4*)(xp + (size_t)r * TT_ + q * 4);
        s[q * 4 + 0][r] = v.x;
        s[q * 4 + 1][r] = v.y;
        s[q * 4 + 2][r] = v.z;
        s[q * 4 + 3][r] = v.w;
    }
    __syncthreads();

    // write: 64 t-rows x 8 c-octets; thread: 2 tasks, each 8 floats -> 1 uint4 per array
    const size_t row0 = (size_t)b * TT_ + t0;
#pragma unroll
    for (int i = 0; i < 2; i++) {
        const int task = tid + i * 256;
        const int tr = task >> 3, cw = task & 7;
        float f[8];
        *(float4*)(f)     = *(const float4*)&s[tr][cw * 8];
        *(float4*)(f + 4) = *(const float4*)&s[tr][cw * 8 + 4];
        uint32_t hw[4], lw[4];
#pragma unroll
        for (int j = 0; j < 4; j++) {
            const float a = f[2 * j], bb2 = f[2 * j + 1];
            __nv_bfloat162 h2 = make_bfloat162(__float2bfloat16(a), __float2bfloat16(bb2));
            __nv_bfloat162 l2 = make_bfloat162(__float2bfloat16(a - __bfloat162float(h2.x)),
                                               __float2bfloat16(bb2 - __bfloat162float(h2.y)));
            hw[j] = *(uint32_t*)&h2;
            lw[j] = *(uint32_t*)&l2;
        }
        const size_t base = (row0 + tr) * CC + c0 + cw * 8;   // bf16 elements, mult of 8
        *(uint4*)(g_xh + base) = make_uint4(hw[0], hw[1], hw[2], hw[3]);
        *(uint4*)(g_xl + base) = make_uint4(lw[0], lw[1], lw[2], lw[3]);
    }
}

// ---------------- mma.sync bf16 projection GEMM ----------------
// D[ch][gt] = Wh.xh + Wl.xh + Wh.xl
// CTA 128(m) x 128(n), 128 threads (4 warps, 2M x 2N), warp 64x64.
// Stage = A0 16KB | A1 16KB | B 16KB = 48KB, double-buffered (96KB) -> 2 CTAs/SM.
#define STG_BYTES 49152
#define GM_SMEM (2 * STG_BYTES)

__global__ __launch_bounds__(128, 2) void gemm_mma() {
    extern __shared__ __align__(128) char smem[];
    const uint32_t sb = smem_u32(smem);
    const int tid = threadIdx.x;
    const int wid = tid >> 5, lane = tid & 31;
    const int n0 = blockIdx.x * 128;       // flattened b*t column base
    const int m0 = blockIdx.y * 128;       // channel base
    const int wm = wid & 1, wn = wid >> 1; // warp tile origin (m:2, n:2)
    const int ml = lane >> 3, rin = lane & 7;

    float acc[4][8][4];
#pragma unroll
    for (int i = 0; i < 4; i++)
#pragma unroll
        for (int j = 0; j < 8; j++)
#pragma unroll
            for (int k = 0; k < 4; k++) acc[i][j][k] = 0.f;

    auto issue = [&](int p) {
        const bool dual = p < 8;
        const int koff = (p & 7) * 64;
        const __nv_bfloat16* bseg = dual ? g_xh : g_xl;
        const uint32_t st = sb + (p & 1) * STG_BYTES;
#pragma unroll
        for (int j = 0; j < 8; j++) {
            int idx = tid + j * 128;
            int r = idx >> 3, cc = idx & 7;
            const uint32_t dsw = SWZ128((uint32_t)(r * 128 + cc * 16));
            CP_ASYNC16(st + dsw, g_Wh + (size_t)(m0 + r) * CC + koff + cc * 8);
            if (dual)
                CP_ASYNC16(st + 16384 + dsw, g_Wl + (size_t)(m0 + r) * CC + koff + cc * 8);
            CP_ASYNC16(st + 32768 + dsw, bseg + (size_t)(n0 + r) * CC + koff + cc * 8);
        }
        asm volatile("cp.async.commit_group;");
    };

    auto compute_pair = [&](uint32_t stA0, uint32_t stA1, uint32_t stB, bool dual) {
#pragma unroll
        for (int ks = 0; ks < 4; ks++) {
            uint32_t bfr[4][4];
#pragma unroll
            for (int bi = 0; bi < 4; bi++) {
                const int n = wn * 64 + bi * 16 + (ml >> 1) * 8 + rin;
                const int kc = 2 * ks + (ml & 1);
                ldsm_x4(bfr[bi][0], bfr[bi][1], bfr[bi][2], bfr[bi][3],
                        stB + n * 128 + ((kc ^ (n & 7)) << 4));
            }
            uint32_t a[4][4];
#pragma unroll
            for (int mi = 0; mi < 4; mi++) {
                const int row = wm * 64 + mi * 16 + (ml & 1) * 8 + rin;
                const int kc = 2 * ks + (ml >> 1);
                ldsm_x4(a[mi][0], a[mi][1], a[mi][2], a[mi][3],
                        stA0 + row * 128 + ((kc ^ (row & 7)) << 4));
            }
#pragma unroll
            for (int mi = 0; mi < 4; mi++)
#pragma unroll
                for (int ni = 0; ni < 8; ni++)
                    MMA16816(acc[mi][ni], a[mi],
                             bfr[ni >> 1][(ni & 1) * 2], bfr[ni >> 1][(ni & 1) * 2 + 1]);
            if (dual) {
#pragma unroll
                for (int mi = 0; mi < 4; mi++) {
                    const int row = wm * 64 + mi * 16 + (ml & 1) * 8 + rin;
                    const int kc = 2 * ks + (ml >> 1);
                    ldsm_x4(a[mi][0], a[mi][1], a[mi][2], a[mi][3],
                            stA1 + row * 128 + ((kc ^ (row & 7)) << 4));
                }
#pragma unroll
                for (int mi = 0; mi < 4; mi++)
#pragma unroll
                    for (int ni = 0; ni < 8; ni++)
                        MMA16816(acc[mi][ni], a[mi],
                                 bfr[ni >> 1][(ni & 1) * 2], bfr[ni >> 1][(ni & 1) * 2 + 1]);
            }
        }
    };

    issue(0);
#pragma unroll 1
    for (int p = 0; p < PSTG; p++) {
        if (p + 1 < PSTG) {
            issue(p + 1);
            asm volatile("cp.async.wait_group 1;");
        } else {
            asm volatile("cp.async.wait_group 0;");
        }
        __syncthreads();
        const uint32_t st = sb + (p & 1) * STG_BYTES;
        compute_pair(st, st + 16384, st + 32768, p < 8);
        __syncthreads();
    }

    // epilogue
    const int b = n0 >> 12;
    const int t0 = n0 & (TT_ - 1);
#pragma unroll
    for (int mi = 0; mi < 4; mi++) {
#pragma unroll
        for (int h = 0; h < 2; h++) {
            const int ch = m0 + wm * 64 + mi * 16 + (lane >> 2) + h * 8;
            if (ch < NCH) {
                float* p = g_proj + ((size_t)b * NCH + ch) * TT_ + t0 + wn * 64 + (lane & 3) * 2;
#pragma unroll
                for (int ni = 0; ni < 8; ni++) {
                    float2 v = make_float2(acc[mi][ni][h * 2], acc[mi][ni][h * 2 + 1]);
                    *(float2*)(p + ni * 8) = v;
                }
            }
        }
    }
}

// ---------------- merged stats: BN partials (ci<192) + k softmax stats (ci>=192) ----------------
__global__ __launch_bounds__(256) void stats_part() {
    const int ci = blockIdx.x, bb = blockIdx.y;
    const int tid = threadIdx.x;
    if (ci < 192) {
        const int ch = ci < 64 ? ci : ci + 16;
        const float* p = g_proj + ((size_t)bb * NCH + ch) * TT_;
        float s = 0.f, s2 = 0.f;
        for (int i = tid * 4; i < TT_; i += 256 * 4) {
            float4 v = *(const float4*)(p + i);
            s += v.x + v.y + v.z + v.w;
            s2 += v.x * v.x + v.y * v.y + v.z * v.z + v.w * v.w;
        }
#pragma unroll
        for (int o = 16; o > 0; o >>= 1) {
            s  += __shfl_down_sync(0xffffffffu, s, o);
            s2 += __shfl_down_sync(0xffffffffu, s2, o);
        }
        __shared__ float ws[8], ws2[8];
        if ((tid & 31) == 0) { ws[tid >> 5] = s; ws2[tid >> 5] = s2; }
        __syncthreads();
        if (tid == 0) {
            float t = 0.f, t2 = 0.f;
#pragma unroll
            for (int w = 0; w < 8; w++) { t += ws[w]; t2 += ws2[w]; }
            g_bnp[(ci * 8 + bb) * 2]     = t;
            g_bnp[(ci * 8 + bb) * 2 + 1] = t2;
        }
    } else {
        const int k = ci - 192;
        const float* row = g_proj + ((size_t)bb * NCH + 64 + k) * TT_;
        float m = -1e30f;
        for (int i = tid * 4; i < TT_; i += 1024) {
            float4 v = *(const float4*)(row + i);
            m = fmaxf(m, fmaxf(fmaxf(v.x, v.y), fmaxf(v.z, v.w)));
        }
#pragma unroll
        for (int o = 16; o > 0; o >>= 1) m = fmaxf(m, __shfl_xor_sync(0xffffffffu, m, o));
        __shared__ float wm[8];
        if ((tid & 31) == 0) wm[tid >> 5] = m;
        __syncthreads();
        m = fmaxf(fmaxf(fmaxf(wm[0], wm[1]), fmaxf(wm[2], wm[3])),
                  fmaxf(fmaxf(wm[4], wm[5]), fmaxf(wm[6], wm[7])));
        float s = 0.f;
        for (int i = tid * 4; i < TT_; i += 1024) {
            float4 v = *(const float4*)(row + i);
            s += expf(v.x - m) + expf(v.y - m) + expf(v.z - m) + expf(v.w - m);
        }
#pragma unroll
        for (int o = 16; o > 0; o >>= 1) s += __shfl_xor_sync(0xffffffffu, s, o);
        __shared__ float wsum[8];
        if ((tid & 31) == 0) wsum[tid >> 5] = s;
        __syncthreads();
        if (tid == 0) {
            float t = 0.f;
#pragma unroll
            for (int w = 0; w < 8; w++) t += wsum[w];
            g_kstat[(bb * KK + k) * 2]     = m;
            g_kstat[(bb * KK + k) * 2 + 1] = 1.f / t;
        }
    }
}

// ---------------- BN stats phase 2: fold to per-channel affine ----------------
__global__ void bn_final(const float* __restrict__ gq, const float* __restrict__ bq,
                         const float* __restrict__ gv, const float* __restrict__ bv) {
    const int ci = threadIdx.x;
    if (ci >= 192) return;
    float s = 0.f, s2 = 0.f;
#pragma unroll
    for (int bb = 0; bb < 8; bb++) {
        s  += g_bnp[(ci * 8 + bb) * 2];
        s2 += g_bnp[(ci * 8 + bb) * 2 + 1];
    }
    const float N = (float)(BB * TT_);
    float mean = s / N;
    float var = s2 / N - mean * mean;
    float g = ci < 64 ? gq[ci] : gv[ci - 64];
    float be = ci < 64 ? bq[ci] : bv[ci - 64];
    float sc = g * rsqrtf(var + 1e-5f);
    g_scale[ci] = sc;
    g_shift[ci] = be - mean * sc;
}

// ---------------- lambda_c partials (softmax applied inline) ----------------
__global__ __launch_bounds__(256) void lamc_part() {
    const int b = blockIdx.y, chunk = blockIdx.x;
    const int t0 = chunk * 128;
    const float* pk = g_proj + ((size_t)b * NCH + 64) * TT_ + t0;
    const float* pv = g_proj + ((size_t)b * NCH + 80) * TT_ + t0;
    __shared__ float sk[KK][33];
    __shared__ float svt[32][132];
    __shared__ float skm[KK], ski[KK];
    const int tid = threadIdx.x;
    const int k = tid & 15, vg = tid >> 4;
    if (tid < KK) {
        skm[tid] = g_kstat[(b * KK + tid) * 2];
        ski[tid] = g_kstat[(b * KK + tid) * 2 + 1];
    }
    __syncthreads();
    float acc[8];
#pragma unroll
    for (int j = 0; j < 8; j++) acc[j] = 0.f;

#pragma unroll 1
    for (int sub = 0; sub < 4; sub++) {
        for (int i = tid; i < KK * 32; i += 256) {
            int kk = i >> 5, tt = i & 31;
            float raw = pk[(size_t)kk * TT_ + sub * 32 + tt];
            sk[kk][tt] = expf(raw - skm[kk]) * ski[kk];
        }
        for (int i = tid; i < NV * 32; i += 256) {
            int v = i >> 5, tt = i & 31;
            svt[tt][v] = pv[(size_t)v * TT_ + sub * 32 + tt];
        }
        __syncthreads();
#pragma unroll
        for (int t = 0; t < 32; t++) {
            const float a = sk[k][t];
            const float4 v0 = *(const float4*)&svt[t][vg * 8];
            const float4 v1 = *(const float4*)&svt[t][vg * 8 + 4];
            acc[0] += a * v0.x; acc[1] += a * v0.y; acc[2] += a * v0.z; acc[3] += a * v0.w;
            acc[4] += a * v1.x; acc[5] += a * v1.y; acc[6] += a * v1.z; acc[7] += a * v1.w;
        }
        __syncthreads();
    }
    float* pp = g_part + (((size_t)b * 32 + chunk) * KK + k) * VV + vg * 8;
#pragma unroll
    for (int j = 0; j < 8; j++) pp[j] = acc[j];
}

// ---------------- reduce partials + fold v BN affine ----------------
__global__ void lamc_reduce() {
    const int i = blockIdx.x * 256 + threadIdx.x;
    if (i >= BB * KK * VV) return;
    const int v = i & 127;
    const int b = i >> 11;
    const float* p = g_part + (size_t)b * 32 * KK * VV + (i & 2047);
    float s = 0.f;
#pragma unroll 1
    for (int c = 0; c < 32; c++) s += p[(size_t)c * KK * VV];
    g_lambda[i] = g_scale[64 + v] * s + g_shift[64 + v];
}

// ---------------- fused output ----------------
#define M_TT 128
#define M_HW 144

__global__ __launch_bounds__(256) void lambda_main(const float* __restrict__ pos_w,
                                                   const float* __restrict__ pos_b,
                                                   float* __restrict__ out) {
    extern __shared__ float sm[];
    float* sq  = sm;
    float* sv  = sm + NQ * M_TT;
    float* slc = sv + NV * M_HW;
    float* spw = slc + KK * VV;
    float* spb = spw + KK * RR;

    const int b = blockIdx.y;
    const int t0 = blockIdx.x * M_TT;
    const int tid = threadIdx.x;
    const float* pq = g_proj + (size_t)b * NCH * TT_;
    const float* pv = pq + (size_t)80 * TT_;

    for (int i = tid; i < NQ * M_TT; i += 256) {
        int ch = i >> 7, t = i & 127;
        sq[i] = pq[(size_t)ch * TT_ + t0 + t] * g_scale[ch] + g_shift[ch];
    }
    for (int i = tid; i < NV * M_HW; i += 256) {
        int v = i / M_HW, tr = i % M_HW;
        float val = 0.f;
        if (tr < M_TT + RR - 1) {
            int tg = t0 - (RR / 2) + tr;
            if (tg >= 0 && tg < TT_)
                val = pv[(size_t)v * TT_ + tg] * g_scale[64 + v] + g_shift[64 + v];
        }
        sv[i] = val;
    }
    for (int i = tid; i < KK * VV; i += 256) slc[i] = g_lambda[(size_t)b * KK * VV + i];
    if (tid < KK * RR) spw[tid] = pos_w[tid];
    if (tid < KK) spb[tid] = pos_b[tid];
    __syncthreads();

    const int t = tid & 127;
    const int vh = tid >> 7;

    float q[NQ];
#pragma unroll
    for (int ch = 0; ch < NQ; ch++) q[ch] = sq[ch * M_TT + t];

    float qw[HH][RR];
    float qb[HH] = {0.f, 0.f, 0.f, 0.f};
#pragma unroll
    for (int h = 0; h < HH; h++)
#pragma unroll
        for (int r = 0; r < RR; r++) qw[h][r] = 0.f;

#pragma unroll
    for (int k = 0; k < KK; k++) {
        const float pb = spb[k];
#pragma unroll
        for (int h = 0; h < HH; h++) qb[h] += q[h * KK + k] * pb;
#pragma unroll
        for (int r = 0; r < RR; r++) {
            const float w = spw[k * RR + r];
#pragma unroll
            for (int h = 0; h < HH; h++) qw[h][r] += q[h * KK + k] * w;
        }
    }

    float* ob = out + (size_t)b * 512 * TT_ + t0 + t;
#pragma unroll 2
    for (int v = 0; v < 64; v++) {
        const int vv = vh * 64 + v;
        float a0 = qb[0], a1 = qb[1], a2 = qb[2], a3 = qb[3];
#pragma unroll
        for (int k = 0; k < KK; k++) {
            const float l = slc[k * VV + vv];
            a0 += q[k] * l;
            a1 += q[KK + k] * l;
            a2 += q[2 * KK + k] * l;
            a3 += q[3 * KK + k] * l;
        }
        const float* vp = sv + vv * M_HW + t;
#pragma unroll
        for (int r = 0; r < RR; r++) {
            const float x = vp[r];
            a0 += qw[0][r] * x;
            a1 += qw[1][r] * x;
            a2 += qw[2][r] * x;
            a3 += qw[3][r] * x;
        }
        ob[(size_t)(0 * VV + vv) * TT_] = a0;
        ob[(size_t)(1 * VV + vv) * TT_] = a1;
        ob[(size_t)(2 * VV + vv) * TT_] = a2;
        ob[(size_t)(3 * VV + vv) * TT_] = a3;
    }
}

// ---------------- launch ----------------
extern "C" void kernel_launch(void* const* d_in, const int* in_sizes, int n_in,
                              void* d_out, int out_size) {
    const float* x  = (const float*)d_in[0];
    const float* Wq = (const float*)d_in[1];
    const float* Wk = (const float*)d_in[2];
    const float* Wv = (const float*)d_in[3];
    const float* gq = (const float*)d_in[4];
    const float* bq = (const float*)d_in[5];
    const float* gv = (const float*)d_in[6];
    const float* bv = (const float*)d_in[7];
    const float* pw = (const float*)d_in[8];
    const float* pb = (const float*)d_in[9];
    float* out = (float*)d_out;

    const size_t main_smem = (size_t)(NQ * M_TT + NV * M_HW + KK * VV + KK * RR + KK) * sizeof(float);
    cudaFuncSetAttribute(lambda_main, cudaFuncAttributeMaxDynamicSharedMemorySize, (int)main_smem);
    cudaFuncSetAttribute(gemm_mma, cudaFuncAttributeMaxDynamicSharedMemorySize, GM_SMEM);

    // stats_part is deliberately the 4th launch (ncu capture slot this round)
    xsplit<<<dim3(TT_ / 64, CC / 64, BB), 256>>>(x);
    pack_w_split<<<(MPAD * CC + 255) / 256, 256>>>(Wq, Wk, Wv);
    gemm_mma<<<dim3(NT / 128, 2), 128, GM_SMEM>>>();
    stats_part<<<dim3(208, 8), 256>>>();
    bn_final<<<1, 192>>>(gq, bq, gv, bv);
    lamc_part<<<dim3(32, BB), 256>>>();
    lamc_reduce<<<(BB * KK * VV + 255) / 256, 256>>>();
    lambda_main<<<dim3(TT_ / M_TT, BB), 256, main_smem>>>(pw, pb, out);
}